// round 7
// baseline (speedup 1.0000x reference)
#include <cuda_runtime.h>
#include <cstdint>
#include <math.h>

#define BATCH   8192
#define D_IN    2048
#define D_HID   16384
#define KSEL    64
#define KAUX    512
#define NCAND   128   // shortlist capacity (top-96 + tie slack)

// ---------------- scratch (static device globals; no dynamic allocation) -------------
__device__ float    g_pre[(size_t)BATCH * D_HID];      // approx (tf32x2) pre-activations
__device__ float    g_WT[(size_t)D_HID * D_IN];        // W_dec transposed [16384,2048]
__device__ int      g_cand[(size_t)BATCH * NCAND];
__device__ int      g_cand_n[BATCH];
__device__ int      g_sel_idx[BATCH * KSEL];
__device__ float    g_sel_val[BATCH * KSEL];
__device__ int      g_aux_idx[(size_t)BATCH * KAUX];
__device__ float    g_aux_val[(size_t)BATCH * KAUX];
__device__ float    g_recon_p[BATCH];
__device__ float    g_aux_p[BATCH];
__device__ float    g_l0_p[BATCH];
__device__ unsigned g_deadbits[D_HID / 32];

// ---------------- helpers ----------------
__device__ __forceinline__ uint32_t f2key(float f) {
    uint32_t u = __float_as_uint(f);
    return (u & 0x80000000u) ? ~u : (u | 0x80000000u);
}
__device__ __forceinline__ float key2f(uint32_t k) {
    uint32_t u = (k & 0x80000000u) ? (k ^ 0x80000000u) : ~k;
    return __uint_as_float(u);
}
__device__ __forceinline__ float tf32r(float x) {
    uint32_t u;
    asm("cvt.rna.tf32.f32 %0, %1;" : "=r"(u) : "f"(x));
    return __uint_as_float(u);
}
__device__ __forceinline__ void mma_tf32(float c[4], uint32_t a0, uint32_t a1,
                                         uint32_t a2, uint32_t a3,
                                         uint32_t b0, uint32_t b1) {
    asm volatile(
        "mma.sync.aligned.m16n8k8.row.col.f32.tf32.tf32.f32 "
        "{%0,%1,%2,%3}, {%4,%5,%6,%7}, {%8,%9}, {%0,%1,%2,%3};\n"
        : "+f"(c[0]), "+f"(c[1]), "+f"(c[2]), "+f"(c[3])
        : "r"(a0), "r"(a1), "r"(a2), "r"(a3), "r"(b0), "r"(b1));
}

// ---------------- dead_mask prep ----------------
__global__ void prep_mask(const uint8_t* __restrict__ m) {
    __shared__ int viol;
    if (threadIdx.x == 0) viol = 0;
    __syncthreads();
    for (int i = threadIdx.x; i < D_HID; i += blockDim.x)
        if ((i & 3) && m[i]) viol = 1;
    __syncthreads();
    const bool is_i32 = (viol == 0);
    const int* mi = (const int*)m;
    for (int w = threadIdx.x; w < D_HID / 32; w += blockDim.x) {
        uint32_t bits = 0;
        #pragma unroll 4
        for (int b = 0; b < 32; ++b) {
            int j = w * 32 + b;
            bool d = is_i32 ? (mi[j] != 0) : (m[j] != 0);
            bits |= ((uint32_t)d) << b;
        }
        g_deadbits[w] = bits;
    }
}

// ---------------- W_dec transpose ----------------
__global__ void transpose_wdec(const float* __restrict__ W) {
    __shared__ float t[32][33];
    int x = blockIdx.x * 32 + threadIdx.x;
    int y0 = blockIdx.y * 32;
    #pragma unroll
    for (int i = threadIdx.y; i < 32; i += 8)
        t[i][threadIdx.x] = W[(size_t)(y0 + i) * D_HID + x];
    __syncthreads();
    int xo = y0 + threadIdx.x;
    int yo0 = blockIdx.x * 32;
    #pragma unroll
    for (int i = threadIdx.y; i < 32; i += 8)
        g_WT[(size_t)(yo0 + i) * D_IN + xo] = t[threadIdx.x][i];
}

// ---------------- approx encoder: tf32x2 split mma.sync GEMM ----------------
// pre ~= (x - b_dec) @ W_enc^T + b_enc, abs err ~2e-6. Used for shortlist +
// aux selection + values; exact-Eigen bits come from refine_kernel.
// CTA 128x128, 8 warps (2Mx4N), warp tile 64x32, BK=16, 3 MMA products.
#define ENC_BM 128
#define ENC_BN 128
#define ENC_BK 16
#define ENC_AS (ENC_BM + 4)
#define ENC_BS (ENC_BN + 4)

__global__ __launch_bounds__(256, 1) void encoder_mma(
    const float* __restrict__ X, const float* __restrict__ WE,
    const float* __restrict__ be, const float* __restrict__ bd)
{
    __shared__ float Ah[ENC_BK * ENC_AS], Al[ENC_BK * ENC_AS];
    __shared__ float Bh[ENC_BK * ENC_BS], Bl[ENC_BK * ENC_BS];

    const int tid = threadIdx.x;
    const int warp = tid >> 5, lane = tid & 31;
    const int wm = warp & 1, wn = warp >> 1;          // 2 x 4 warp grid
    const int g = lane >> 2, tg = lane & 3;           // groupID, tid-in-group
    const int m0 = blockIdx.y * ENC_BM, n0 = blockIdx.x * ENC_BN;

    float c[4][4][4];
    #pragma unroll
    for (int mi = 0; mi < 4; ++mi)
        #pragma unroll
        for (int nj = 0; nj < 4; ++nj)
            #pragma unroll
            for (int q = 0; q < 4; ++q) c[mi][nj][q] = 0.f;

    float4 a_st[2], b_st[2];

    // prologue load tile 0
    {
        #pragma unroll
        for (int i = 0; i < 2; ++i) {
            int s = tid + i * 256;
            int row = s >> 2, kq = (s & 3) << 2;
            float4 xv = *(const float4*)(X + (size_t)(m0 + row) * D_IN + kq);
            float4 dv = *(const float4*)(bd + kq);
            a_st[i] = make_float4(xv.x - dv.x, xv.y - dv.y, xv.z - dv.z, xv.w - dv.w);
            b_st[i] = *(const float4*)(WE + (size_t)(n0 + row) * D_IN + kq);
        }
    }

    for (int kt = 0; kt < D_IN / ENC_BK; ++kt) {
        __syncthreads();
        // store staged tile (split hi/lo)
        #pragma unroll
        for (int i = 0; i < 2; ++i) {
            int s = tid + i * 256;
            int row = s >> 2, kl = (s & 3) << 2;
            float av[4] = {a_st[i].x, a_st[i].y, a_st[i].z, a_st[i].w};
            float bv[4] = {b_st[i].x, b_st[i].y, b_st[i].z, b_st[i].w};
            #pragma unroll
            for (int e = 0; e < 4; ++e) {
                float h = tf32r(av[e]);
                Ah[(kl + e) * ENC_AS + row] = h;
                Al[(kl + e) * ENC_AS + row] = tf32r(av[e] - h);
                float hb = tf32r(bv[e]);
                Bh[(kl + e) * ENC_BS + row] = hb;
                Bl[(kl + e) * ENC_BS + row] = tf32r(bv[e] - hb);
            }
        }
        __syncthreads();
        // prefetch next tile
        if (kt + 1 < D_IN / ENC_BK) {
            int k0 = (kt + 1) * ENC_BK;
            #pragma unroll
            for (int i = 0; i < 2; ++i) {
                int s = tid + i * 256;
                int row = s >> 2, kq = ((s & 3) << 2) + k0;
                float4 xv = *(const float4*)(X + (size_t)(m0 + row) * D_IN + kq);
                float4 dv = *(const float4*)(bd + kq);
                a_st[i] = make_float4(xv.x - dv.x, xv.y - dv.y, xv.z - dv.z, xv.w - dv.w);
                b_st[i] = *(const float4*)(WE + (size_t)(n0 + row) * D_IN + kq);
            }
        }
        // compute on smem tile: 2 k8 steps
        #pragma unroll
        for (int s = 0; s < 2; ++s) {
            const int ka = s * 8 + tg;
            uint32_t ah[4][4], al4[4][4], bh[4][2], bl4[4][2];
            #pragma unroll
            for (int mi = 0; mi < 4; ++mi) {
                int m = wm * 64 + mi * 16 + g;
                ah[mi][0] = __float_as_uint(Ah[ka * ENC_AS + m]);
                ah[mi][1] = __float_as_uint(Ah[ka * ENC_AS + m + 8]);
                ah[mi][2] = __float_as_uint(Ah[(ka + 4) * ENC_AS + m]);
                ah[mi][3] = __float_as_uint(Ah[(ka + 4) * ENC_AS + m + 8]);
                al4[mi][0] = __float_as_uint(Al[ka * ENC_AS + m]);
                al4[mi][1] = __float_as_uint(Al[ka * ENC_AS + m + 8]);
                al4[mi][2] = __float_as_uint(Al[(ka + 4) * ENC_AS + m]);
                al4[mi][3] = __float_as_uint(Al[(ka + 4) * ENC_AS + m + 8]);
            }
            #pragma unroll
            for (int nj = 0; nj < 4; ++nj) {
                int nn = wn * 32 + nj * 8 + g;
                bh[nj][0] = __float_as_uint(Bh[ka * ENC_BS + nn]);
                bh[nj][1] = __float_as_uint(Bh[(ka + 4) * ENC_BS + nn]);
                bl4[nj][0] = __float_as_uint(Bl[ka * ENC_BS + nn]);
                bl4[nj][1] = __float_as_uint(Bl[(ka + 4) * ENC_BS + nn]);
            }
            #pragma unroll
            for (int nj = 0; nj < 4; ++nj)
                #pragma unroll
                for (int mi = 0; mi < 4; ++mi) {
                    mma_tf32(c[mi][nj], ah[mi][0], ah[mi][1], ah[mi][2], ah[mi][3],
                             bh[nj][0], bh[nj][1]);
                    mma_tf32(c[mi][nj], ah[mi][0], ah[mi][1], ah[mi][2], ah[mi][3],
                             bl4[nj][0], bl4[nj][1]);
                    mma_tf32(c[mi][nj], al4[mi][0], al4[mi][1], al4[mi][2], al4[mi][3],
                             bh[nj][0], bh[nj][1]);
                }
        }
    }

    // epilogue: add b_enc, write
    #pragma unroll
    for (int mi = 0; mi < 4; ++mi) {
        #pragma unroll
        for (int nj = 0; nj < 4; ++nj) {
            int row0 = m0 + wm * 64 + mi * 16 + g;
            int col = n0 + wn * 32 + nj * 8 + 2 * tg;
            float2 be2 = *(const float2*)(be + col);
            float2 o0 = make_float2(c[mi][nj][0] + be2.x, c[mi][nj][1] + be2.y);
            float2 o1 = make_float2(c[mi][nj][2] + be2.x, c[mi][nj][3] + be2.y);
            *(float2*)&g_pre[(size_t)row0 * D_HID + col] = o0;
            *(float2*)&g_pre[(size_t)(row0 + 8) * D_HID + col] = o1;
        }
    }
}

// ---------------- exact radix-select ----------------
__device__ void radix_select(const uint32_t* keys, const uint32_t* deadb, bool useMask,
                             uint32_t* hist, int K, uint32_t* outT, int* outNeed, int lane)
{
    uint32_t prefix = 0;
    int kk = K;
    #pragma unroll 1
    for (int level = 0; level < 4; ++level) {
        const int shift = 24 - 8 * level;
        for (int b = threadIdx.x; b < 256; b += blockDim.x) hist[b] = 0;
        __syncthreads();
        const uint32_t hmask = (level == 0) ? 0u : (0xFFFFFFFFu << (shift + 8));
        for (int j = threadIdx.x; j < D_HID; j += blockDim.x) {
            uint32_t k = keys[j];
            if (useMask && !((deadb[j >> 5] >> (j & 31)) & 1u)) k = 0u;
            const bool valid = ((k & hmask) == prefix);
            const int bin = (int)((k >> shift) & 255u);
            const int tag = valid ? bin : (256 + lane);
            const unsigned grp = __match_any_sync(0xFFFFFFFFu, tag);
            if (valid && lane == (__ffs(grp) - 1))
                atomicAdd(&hist[bin], (uint32_t)__popc(grp));
        }
        __syncthreads();
        if (threadIdx.x == 0) {
            int acc = 0, b = 255;
            for (; b > 0; --b) {
                int c = (int)hist[b];
                if (acc + c >= kk) break;
                acc += c;
            }
            hist[256] = (uint32_t)b;
            hist[257] = (uint32_t)(kk - acc);
        }
        __syncthreads();
        prefix |= (hist[256] << shift);
        kk = (int)hist[257];
        __syncthreads();
    }
    *outT = prefix;
    *outNeed = kk;
}

// ---------------- per-row: main shortlist (top-96 approx) + aux top-512 -------------
__global__ __launch_bounds__(256) void topk_kernel(float* __restrict__ z_out)
{
    extern __shared__ uint32_t sm[];
    uint32_t* keys  = sm;
    uint32_t* deadb = sm + 16384;
    uint32_t* hist  = sm + 16896;
    int*      eq    = (int*)(sm + 17160);
    int*      ctr   = (int*)(sm + 17224);

    const int tid = threadIdx.x;
    const int lane = tid & 31;
    const int r = blockIdx.x;
    const size_t base = (size_t)r * D_HID;

    for (int j = tid; j < D_HID; j += 256) keys[j] = f2key(g_pre[base + j]);
    for (int w = tid; w < D_HID / 32; w += 256) deadb[w] = g_deadbits[w];
    __syncthreads();

    // ===== main: shortlist top-96 candidates (exact bits from refine) =====
    uint32_t T; int needEq;
    radix_select(keys, deadb, false, hist, 96, &T, &needEq, lane);
    if (tid == 0) ctr[0] = 0;
    __syncthreads();
    for (int j = tid; j < D_HID; j += 256) {
        z_out[base + j] = 0.f;
        if (keys[j] >= T) {
            int p = atomicAdd(&ctr[0], 1);
            if (p < NCAND) g_cand[(size_t)r * NCAND + p] = j;
        }
    }
    __syncthreads();
    if (tid == 0) g_cand_n[r] = min(ctr[0], NCAND);
    __syncthreads();

    // ===== aux top-512 among dead features (approx values; only aux_loss scalar) =====
    uint32_t Ta; int needEqA;
    radix_select(keys, deadb, true, hist, KAUX, &Ta, &needEqA, lane);
    if (tid == 0) { ctr[0] = 0; ctr[1] = 0; }
    __syncthreads();
    for (int j = tid; j < D_HID; j += 256) {
        uint32_t k = ((deadb[j >> 5] >> (j & 31)) & 1u) ? keys[j] : 0u;
        if (k != 0u && k == Ta) { int p = atomicAdd(&ctr[1], 1); if (p < 64) eq[p] = j; }
    }
    __syncthreads();
    if (tid == 0) {
        int m = min(ctr[1], 64);
        int take = min(needEqA, m);
        for (int a = 0; a < take; ++a) {
            int best = a;
            for (int b = a + 1; b < m; ++b) if (eq[b] < eq[best]) best = b;
            int t2 = eq[a]; eq[a] = eq[best]; eq[best] = t2;
        }
        ctr[1] = take;
    }
    __syncthreads();
    const int nEqA = ctr[1];
    for (int j = tid; j < D_HID; j += 256) {
        uint32_t k = ((deadb[j >> 5] >> (j & 31)) & 1u) ? keys[j] : 0u;
        bool sel = (k > Ta);
        if (!sel && k != 0u && k == Ta)
            for (int a = 0; a < nEqA; ++a) if (eq[a] == j) { sel = true; break; }
        if (sel) {
            int p = atomicAdd(&ctr[0], 1);
            if (p < KAUX) { g_aux_idx[(size_t)r * KAUX + p] = j; g_aux_val[(size_t)r * KAUX + p] = key2f(keys[j]); }
        }
    }
    __syncthreads();
    if (tid == 0)
        for (int p = min(ctr[0], KAUX); p < KAUX; ++p) {
            g_aux_idx[(size_t)r * KAUX + p] = 0; g_aux_val[(size_t)r * KAUX + p] = -1.f;
        }
}

// ---------------- exact-Eigen refine: recompute candidates, emit bitwise top-64 -----
// Per candidate: serial ascending FMA chain, panel folds at k = 248*i (the
// R6-verified Eigen gebp kc=248 order) -> bitwise equals reference pre_acts.
__global__ __launch_bounds__(128) void refine_kernel(
    const float* __restrict__ X, const float* __restrict__ WE,
    const float* __restrict__ be, const float* __restrict__ bd,
    float* __restrict__ z_out)
{
    __shared__ __align__(16) float xs[D_IN];
    __shared__ float vals[NCAND];
    __shared__ int   idxs[NCAND];
    __shared__ int   l0c;
    const int tid = threadIdx.x, r = blockIdx.x;
    if (tid == 0) l0c = 0;
    for (int k = tid; k < D_IN; k += 128)
        xs[k] = X[(size_t)r * D_IN + k] - bd[k];
    const int n = g_cand_n[r];
    if (tid < n) idxs[tid] = g_cand[(size_t)r * NCAND + tid];
    __syncthreads();

    if (tid < n) {
        const int fi = idxs[tid];
        const float4* w4 = (const float4*)(WE + (size_t)fi * D_IN);
        float acc = 0.f, pan = 0.f;
        int next = 248;
        for (int k = 0; k < D_IN; k += 4) {
            if (k == next) { acc += pan; pan = 0.f; next += 248; }
            float4 w = w4[k >> 2];
            pan = fmaf(xs[k + 0], w.x, pan);
            pan = fmaf(xs[k + 1], w.y, pan);
            pan = fmaf(xs[k + 2], w.z, pan);
            pan = fmaf(xs[k + 3], w.w, pan);
        }
        acc += pan;
        vals[tid] = acc + be[fi];
    }
    __syncthreads();

    if (tid < n) {
        const float v = vals[tid];
        const int myi = idxs[tid];
        int rank = 0;
        for (int j = 0; j < n; ++j) {
            const float u = vals[j];
            if (u > v || (u == v && idxs[j] < myi)) ++rank;
        }
        if (rank < KSEL) {
            g_sel_idx[r * KSEL + rank] = myi;
            g_sel_val[r * KSEL + rank] = v;
            z_out[(size_t)r * D_HID + myi] = fmaxf(v, 0.f);
            if (v > 0.f) atomicAdd(&l0c, 1);
        }
    }
    __syncthreads();
    if (tid == 0) g_l0_p[r] = (float)l0c;
}

// ---------------- sparse decode: x_hat = z @ W_dec^T + b_dec, recon partials --------
__global__ __launch_bounds__(256) void decode_main(const float* __restrict__ X,
                                                   float* __restrict__ xhat,
                                                   const float* __restrict__ bd)
{
    __shared__ int s_idx[KSEL];
    __shared__ float s_val[KSEL];
    __shared__ float red[8];
    const int tid = threadIdx.x, r = blockIdx.x;
    if (tid < KSEL) {
        s_idx[tid] = g_sel_idx[r * KSEL + tid];
        s_val[tid] = fmaxf(g_sel_val[r * KSEL + tid], 0.f);
    }
    __syncthreads();
    const float4* bd4 = (const float4*)bd;
    float4 acc0 = bd4[tid], acc1 = bd4[tid + 256];
    #pragma unroll 4
    for (int s = 0; s < KSEL; ++s) {
        float v = s_val[s];
        const float4* w = (const float4*)(g_WT + (size_t)s_idx[s] * D_IN);
        float4 w0 = w[tid], w1 = w[tid + 256];
        acc0.x += v * w0.x; acc0.y += v * w0.y; acc0.z += v * w0.z; acc0.w += v * w0.w;
        acc1.x += v * w1.x; acc1.y += v * w1.y; acc1.z += v * w1.z; acc1.w += v * w1.w;
    }
    const size_t b4 = (size_t)r * (D_IN / 4);
    ((float4*)xhat)[b4 + tid] = acc0;
    ((float4*)xhat)[b4 + tid + 256] = acc1;
    const float4* X4 = (const float4*)X;
    float4 x0 = X4[b4 + tid], x1 = X4[b4 + tid + 256];
    float d, loc = 0.f;
    d = acc0.x - x0.x; loc += d * d;  d = acc0.y - x0.y; loc += d * d;
    d = acc0.z - x0.z; loc += d * d;  d = acc0.w - x0.w; loc += d * d;
    d = acc1.x - x1.x; loc += d * d;  d = acc1.y - x1.y; loc += d * d;
    d = acc1.z - x1.z; loc += d * d;  d = acc1.w - x1.w; loc += d * d;
    #pragma unroll
    for (int o = 16; o; o >>= 1) loc += __shfl_down_sync(0xFFFFFFFFu, loc, o);
    if ((tid & 31) == 0) red[tid >> 5] = loc;
    __syncthreads();
    if (tid == 0) {
        float s = 0.f;
        for (int w2 = 0; w2 < 8; ++w2) s += red[w2];
        g_recon_p[r] = s;
    }
}

// ---------------- aux decode: e_hat row + aux partials ----------------
__global__ __launch_bounds__(256) void decode_aux(const float* __restrict__ X,
                                                  const float* __restrict__ xhat)
{
    __shared__ int s_idx[KAUX];
    __shared__ float s_val[KAUX];
    __shared__ float red[8];
    const int tid = threadIdx.x, r = blockIdx.x;
    for (int s = tid; s < KAUX; s += 256) {
        s_idx[s] = g_aux_idx[(size_t)r * KAUX + s];
        s_val[s] = fmaxf(g_aux_val[(size_t)r * KAUX + s], 0.f);
    }
    __syncthreads();
    float4 acc0 = make_float4(0.f, 0.f, 0.f, 0.f);
    float4 acc1 = make_float4(0.f, 0.f, 0.f, 0.f);
    #pragma unroll 4
    for (int s = 0; s < KAUX; ++s) {
        float v = s_val[s];
        const float4* w = (const float4*)(g_WT + (size_t)s_idx[s] * D_IN);
        float4 w0 = w[tid], w1 = w[tid + 256];
        acc0.x += v * w0.x; acc0.y += v * w0.y; acc0.z += v * w0.z; acc0.w += v * w0.w;
        acc1.x += v * w1.x; acc1.y += v * w1.y; acc1.z += v * w1.z; acc1.w += v * w1.w;
    }
    const size_t b4 = (size_t)r * (D_IN / 4);
    const float4* X4 = (const float4*)X;
    const float4* H4 = (const float4*)xhat;
    float4 x0 = X4[b4 + tid], x1 = X4[b4 + tid + 256];
    float4 h0 = H4[b4 + tid], h1 = H4[b4 + tid + 256];
    float d, loc = 0.f;
    d = acc0.x - (x0.x - h0.x); loc += d * d;  d = acc0.y - (x0.y - h0.y); loc += d * d;
    d = acc0.z - (x0.z - h0.z); loc += d * d;  d = acc0.w - (x0.w - h0.w); loc += d * d;
    d = acc1.x - (x1.x - h1.x); loc += d * d;  d = acc1.y - (x1.y - h1.y); loc += d * d;
    d = acc1.z - (x1.z - h1.z); loc += d * d;  d = acc1.w - (x1.w - h1.w); loc += d * d;
    #pragma unroll
    for (int o = 16; o; o >>= 1) loc += __shfl_down_sync(0xFFFFFFFFu, loc, o);
    if ((tid & 31) == 0) red[tid >> 5] = loc;
    __syncthreads();
    if (tid == 0) {
        float s = 0.f;
        for (int w2 = 0; w2 < 8; ++w2) s += red[w2];
        g_aux_p[r] = s;
    }
}

// ---------------- final scalar reduction ----------------
__global__ void finalize_kernel(float* __restrict__ outs)
{
    __shared__ double sd[256];
    const int tid = threadIdx.x;
    double s = 0.0;
    for (int i = tid; i < BATCH; i += 256) s += (double)g_recon_p[i];
    sd[tid] = s; __syncthreads();
    for (int o = 128; o > 0; o >>= 1) { if (tid < o) sd[tid] += sd[tid + o]; __syncthreads(); }
    double recon = sd[0] / ((double)BATCH * (double)D_IN);
    __syncthreads();

    s = 0.0;
    for (int i = tid; i < BATCH; i += 256) s += (double)g_aux_p[i];
    sd[tid] = s; __syncthreads();
    for (int o = 128; o > 0; o >>= 1) { if (tid < o) sd[tid] += sd[tid + o]; __syncthreads(); }
    double aux = sd[0] / ((double)BATCH * (double)D_IN);
    __syncthreads();

    s = 0.0;
    for (int i = tid; i < BATCH; i += 256) s += (double)g_l0_p[i];
    sd[tid] = s; __syncthreads();
    for (int o = 128; o > 0; o >>= 1) { if (tid < o) sd[tid] += sd[tid + o]; __syncthreads(); }
    double l0 = sd[0] / (double)BATCH;

    if (tid == 0) {
        outs[0] = (float)(recon + aux * (1.0 / 32.0));
        outs[1] = (float)recon;
        outs[2] = (float)aux;
        outs[3] = (float)l0;
    }
}

// ---------------- launch ----------------
extern "C" void kernel_launch(void* const* d_in, const int* in_sizes, int n_in,
                              void* d_out, int out_size) {
    (void)in_sizes; (void)n_in; (void)out_size;
    const float* X  = (const float*)d_in[0];
    const float* WE = (const float*)d_in[1];
    const float* be = (const float*)d_in[2];
    const float* WD = (const float*)d_in[3];
    const float* bd = (const float*)d_in[4];
    const uint8_t* dm = (const uint8_t*)d_in[5];

    float* out = (float*)d_out;
    float* xhat = out;                                    // [8192, 2048]
    float* z = out + (size_t)BATCH * D_IN;                // [8192, 16384]
    float* scalars = z + (size_t)BATCH * D_HID;           // loss, recon, aux, l0

    cudaFuncSetAttribute(topk_kernel, cudaFuncAttributeMaxDynamicSharedMemorySize, 70 * 1024);

    prep_mask<<<1, 512>>>(dm);
    transpose_wdec<<<dim3(D_HID / 32, D_IN / 32), dim3(32, 8)>>>(WD);
    encoder_mma<<<dim3(D_HID / ENC_BN, BATCH / ENC_BM), 256>>>(X, WE, be, bd);
    topk_kernel<<<BATCH, 256, 70 * 1024>>>(z);
    refine_kernel<<<BATCH, 128>>>(X, WE, be, bd, z);
    decode_main<<<BATCH, 256>>>(X, xhat, bd);
    decode_aux<<<BATCH, 256>>>(X, xhat);
    finalize_kernel<<<1, 256>>>(scalars);
}

// round 8
// speedup vs baseline: 1.3189x; 1.3189x over previous
#include <cuda_runtime.h>
#include <cuda_bf16.h>
#include <cstdint>
#include <math.h>

#define BATCH   8192
#define D_IN    2048
#define D_HID   16384
#define KSEL    64
#define KAUX    512
#define NCAND   128   // shortlist capacity (top-96 + tie slack)

// ---------------- scratch (static device globals; no dynamic allocation) -------------
__device__ float    g_pre[(size_t)BATCH * D_HID];      // approx (bf16x2) pre-activations
__device__ float    g_WT[(size_t)D_HID * D_IN];        // W_dec transposed [16384,2048]
__device__ int      g_cand[(size_t)BATCH * NCAND];
__device__ int      g_cand_n[BATCH];
__device__ int      g_sel_idx[BATCH * KSEL];
__device__ float    g_sel_val[BATCH * KSEL];
__device__ int      g_aux_idx[(size_t)BATCH * KAUX];
__device__ float    g_aux_val[(size_t)BATCH * KAUX];
__device__ float    g_recon_p[BATCH];
__device__ float    g_aux_p[BATCH];
__device__ float    g_l0_p[BATCH];
__device__ unsigned g_deadbits[D_HID / 32];

// ---------------- helpers ----------------
__device__ __forceinline__ uint32_t f2key(float f) {
    uint32_t u = __float_as_uint(f);
    return (u & 0x80000000u) ? ~u : (u | 0x80000000u);
}
__device__ __forceinline__ float key2f(uint32_t k) {
    uint32_t u = (k & 0x80000000u) ? (k ^ 0x80000000u) : ~k;
    return __uint_as_float(u);
}
// bf16x2 split of a float pair: hi = bf16(v), lo = bf16(v - hi), packed (even=low half)
__device__ __forceinline__ void split_pair(float x, float y, uint32_t& hp, uint32_t& lp) {
    __nv_bfloat16 hx = __float2bfloat16_rn(x), hy = __float2bfloat16_rn(y);
    float rx = x - __bfloat162float(hx), ry = y - __bfloat162float(hy);
    __nv_bfloat162 h2 = __halves2bfloat162(hx, hy);
    __nv_bfloat162 l2 = __floats2bfloat162_rn(rx, ry);
    hp = *reinterpret_cast<uint32_t*>(&h2);
    lp = *reinterpret_cast<uint32_t*>(&l2);
}
__device__ __forceinline__ void mma_bf16(float c[4], uint32_t a0, uint32_t a1,
                                         uint32_t a2, uint32_t a3,
                                         uint32_t b0, uint32_t b1) {
    asm volatile(
        "mma.sync.aligned.m16n8k16.row.col.f32.bf16.bf16.f32 "
        "{%0,%1,%2,%3}, {%4,%5,%6,%7}, {%8,%9}, {%0,%1,%2,%3};\n"
        : "+f"(c[0]), "+f"(c[1]), "+f"(c[2]), "+f"(c[3])
        : "r"(a0), "r"(a1), "r"(a2), "r"(a3), "r"(b0), "r"(b1));
}

// ---------------- dead_mask prep ----------------
__global__ void prep_mask(const uint8_t* __restrict__ m) {
    __shared__ int viol;
    if (threadIdx.x == 0) viol = 0;
    __syncthreads();
    for (int i = threadIdx.x; i < D_HID; i += blockDim.x)
        if ((i & 3) && m[i]) viol = 1;
    __syncthreads();
    const bool is_i32 = (viol == 0);
    const int* mi = (const int*)m;
    for (int w = threadIdx.x; w < D_HID / 32; w += blockDim.x) {
        uint32_t bits = 0;
        #pragma unroll 4
        for (int b = 0; b < 32; ++b) {
            int j = w * 32 + b;
            bool d = is_i32 ? (mi[j] != 0) : (m[j] != 0);
            bits |= ((uint32_t)d) << b;
        }
        g_deadbits[w] = bits;
    }
}

// ---------------- W_dec transpose ----------------
__global__ void transpose_wdec(const float* __restrict__ W) {
    __shared__ float t[32][33];
    int x = blockIdx.x * 32 + threadIdx.x;
    int y0 = blockIdx.y * 32;
    #pragma unroll
    for (int i = threadIdx.y; i < 32; i += 8)
        t[i][threadIdx.x] = W[(size_t)(y0 + i) * D_HID + x];
    __syncthreads();
    int xo = y0 + threadIdx.x;
    int yo0 = blockIdx.x * 32;
    #pragma unroll
    for (int i = threadIdx.y; i < 32; i += 8)
        g_WT[(size_t)(yo0 + i) * D_IN + xo] = t[threadIdx.x][i];
}

// ---------------- approx encoder: bf16x2 split mma.sync m16n8k16 GEMM ----------------
// pre ~= (x - b_dec) @ W_enc^T + b_enc, abs err ~1e-5 (3 products: A1B1+A1B2+A2B1).
// CTA 128x128, 8 warps (2Mx4N), warp tile 64x32, BK=16 (8 bf16x2 pairs).
// Smem stride 136 uint32 => all fragment LDS conflict-free.
#define ENC_BM 128
#define ENC_BN 128
#define ENC_ST 136

__global__ __launch_bounds__(256, 1) void encoder_mma(
    const float* __restrict__ X, const float* __restrict__ WE,
    const float* __restrict__ be, const float* __restrict__ bd)
{
    __shared__ uint32_t A1s[8 * ENC_ST], A2s[8 * ENC_ST];
    __shared__ uint32_t B1s[8 * ENC_ST], B2s[8 * ENC_ST];

    const int tid = threadIdx.x;
    const int warp = tid >> 5, lane = tid & 31;
    const int wm = warp & 1, wn = warp >> 1;          // 2 x 4 warp grid
    const int g = lane >> 2, tg = lane & 3;           // groupID, tid-in-group
    const int m0 = blockIdx.y * ENC_BM, n0 = blockIdx.x * ENC_BN;

    float c[4][4][4];
    #pragma unroll
    for (int mi = 0; mi < 4; ++mi)
        #pragma unroll
        for (int nj = 0; nj < 4; ++nj)
            #pragma unroll
            for (int q = 0; q < 4; ++q) c[mi][nj][q] = 0.f;

    float4 a_st[2], b_st[2];

    // prologue load tile 0
    #pragma unroll
    for (int i = 0; i < 2; ++i) {
        int s = tid + i * 256;
        int row = s >> 2, kq = (s & 3) << 2;
        float4 xv = *(const float4*)(X + (size_t)(m0 + row) * D_IN + kq);
        float4 dv = *(const float4*)(bd + kq);
        a_st[i] = make_float4(xv.x - dv.x, xv.y - dv.y, xv.z - dv.z, xv.w - dv.w);
        b_st[i] = *(const float4*)(WE + (size_t)(n0 + row) * D_IN + kq);
    }

    for (int kt = 0; kt < D_IN / 16; ++kt) {
        __syncthreads();
        // store staged tile as bf16x2 split pairs
        #pragma unroll
        for (int i = 0; i < 2; ++i) {
            int s = tid + i * 256;
            int row = s >> 2;
            int kp = (s & 3) << 1;     // pair index 0,2,4,6
            uint32_t h, l;
            split_pair(a_st[i].x, a_st[i].y, h, l);
            A1s[kp * ENC_ST + row] = h; A2s[kp * ENC_ST + row] = l;
            split_pair(a_st[i].z, a_st[i].w, h, l);
            A1s[(kp + 1) * ENC_ST + row] = h; A2s[(kp + 1) * ENC_ST + row] = l;
            split_pair(b_st[i].x, b_st[i].y, h, l);
            B1s[kp * ENC_ST + row] = h; B2s[kp * ENC_ST + row] = l;
            split_pair(b_st[i].z, b_st[i].w, h, l);
            B1s[(kp + 1) * ENC_ST + row] = h; B2s[(kp + 1) * ENC_ST + row] = l;
        }
        __syncthreads();
        // prefetch next tile
        if (kt + 1 < D_IN / 16) {
            int k0 = (kt + 1) * 16;
            #pragma unroll
            for (int i = 0; i < 2; ++i) {
                int s = tid + i * 256;
                int row = s >> 2, kq = ((s & 3) << 2) + k0;
                float4 xv = *(const float4*)(X + (size_t)(m0 + row) * D_IN + kq);
                float4 dv = *(const float4*)(bd + kq);
                a_st[i] = make_float4(xv.x - dv.x, xv.y - dv.y, xv.z - dv.z, xv.w - dv.w);
                b_st[i] = *(const float4*)(WE + (size_t)(n0 + row) * D_IN + kq);
            }
        }
        // fragments: one m16n8k16 step covers the whole BK=16 tile
        uint32_t a1f[4][4], a2f[4][4], b1f[4][2], b2f[4][2];
        #pragma unroll
        for (int mi = 0; mi < 4; ++mi) {
            int m = wm * 64 + mi * 16 + g;
            a1f[mi][0] = A1s[tg * ENC_ST + m];
            a1f[mi][1] = A1s[tg * ENC_ST + m + 8];
            a1f[mi][2] = A1s[(tg + 4) * ENC_ST + m];
            a1f[mi][3] = A1s[(tg + 4) * ENC_ST + m + 8];
            a2f[mi][0] = A2s[tg * ENC_ST + m];
            a2f[mi][1] = A2s[tg * ENC_ST + m + 8];
            a2f[mi][2] = A2s[(tg + 4) * ENC_ST + m];
            a2f[mi][3] = A2s[(tg + 4) * ENC_ST + m + 8];
        }
        #pragma unroll
        for (int nj = 0; nj < 4; ++nj) {
            int nn = wn * 32 + nj * 8 + g;
            b1f[nj][0] = B1s[tg * ENC_ST + nn];
            b1f[nj][1] = B1s[(tg + 4) * ENC_ST + nn];
            b2f[nj][0] = B2s[tg * ENC_ST + nn];
            b2f[nj][1] = B2s[(tg + 4) * ENC_ST + nn];
        }
        #pragma unroll
        for (int nj = 0; nj < 4; ++nj)
            #pragma unroll
            for (int mi = 0; mi < 4; ++mi) {
                mma_bf16(c[mi][nj], a1f[mi][0], a1f[mi][1], a1f[mi][2], a1f[mi][3],
                         b1f[nj][0], b1f[nj][1]);
                mma_bf16(c[mi][nj], a1f[mi][0], a1f[mi][1], a1f[mi][2], a1f[mi][3],
                         b2f[nj][0], b2f[nj][1]);
                mma_bf16(c[mi][nj], a2f[mi][0], a2f[mi][1], a2f[mi][2], a2f[mi][3],
                         b1f[nj][0], b1f[nj][1]);
            }
    }

    // epilogue: add b_enc, write
    #pragma unroll
    for (int mi = 0; mi < 4; ++mi) {
        #pragma unroll
        for (int nj = 0; nj < 4; ++nj) {
            int row0 = m0 + wm * 64 + mi * 16 + g;
            int col = n0 + wn * 32 + nj * 8 + 2 * tg;
            float2 be2 = *(const float2*)(be + col);
            float2 o0 = make_float2(c[mi][nj][0] + be2.x, c[mi][nj][1] + be2.y);
            float2 o1 = make_float2(c[mi][nj][2] + be2.x, c[mi][nj][3] + be2.y);
            *(float2*)&g_pre[(size_t)row0 * D_HID + col] = o0;
            *(float2*)&g_pre[(size_t)(row0 + 8) * D_HID + col] = o1;
        }
    }
}

// ---------------- exact radix-select ----------------
__device__ void radix_select(const uint32_t* keys, const uint32_t* deadb, bool useMask,
                             uint32_t* hist, int K, uint32_t* outT, int* outNeed, int lane)
{
    uint32_t prefix = 0;
    int kk = K;
    #pragma unroll 1
    for (int level = 0; level < 4; ++level) {
        const int shift = 24 - 8 * level;
        for (int b = threadIdx.x; b < 256; b += blockDim.x) hist[b] = 0;
        __syncthreads();
        const uint32_t hmask = (level == 0) ? 0u : (0xFFFFFFFFu << (shift + 8));
        for (int j = threadIdx.x; j < D_HID; j += blockDim.x) {
            uint32_t k = keys[j];
            if (useMask && !((deadb[j >> 5] >> (j & 31)) & 1u)) k = 0u;
            const bool valid = ((k & hmask) == prefix);
            const int bin = (int)((k >> shift) & 255u);
            const int tag = valid ? bin : (256 + lane);
            const unsigned grp = __match_any_sync(0xFFFFFFFFu, tag);
            if (valid && lane == (__ffs(grp) - 1))
                atomicAdd(&hist[bin], (uint32_t)__popc(grp));
        }
        __syncthreads();
        if (threadIdx.x == 0) {
            int acc = 0, b = 255;
            for (; b > 0; --b) {
                int c = (int)hist[b];
                if (acc + c >= kk) break;
                acc += c;
            }
            hist[256] = (uint32_t)b;
            hist[257] = (uint32_t)(kk - acc);
        }
        __syncthreads();
        prefix |= (hist[256] << shift);
        kk = (int)hist[257];
        __syncthreads();
    }
    *outT = prefix;
    *outNeed = kk;
}

// ---------------- per-row: main shortlist (top-96 approx) + aux top-512 -------------
__global__ __launch_bounds__(256) void topk_kernel(float* __restrict__ z_out)
{
    extern __shared__ uint32_t sm[];
    uint32_t* keys  = sm;
    uint32_t* deadb = sm + 16384;
    uint32_t* hist  = sm + 16896;
    int*      eq    = (int*)(sm + 17160);
    int*      ctr   = (int*)(sm + 17224);

    const int tid = threadIdx.x;
    const int lane = tid & 31;
    const int r = blockIdx.x;
    const size_t base = (size_t)r * D_HID;

    for (int j = tid; j < D_HID; j += 256) keys[j] = f2key(g_pre[base + j]);
    for (int w = tid; w < D_HID / 32; w += 256) deadb[w] = g_deadbits[w];
    __syncthreads();

    // ===== main: shortlist top-96 candidates (exact bits from refine) =====
    uint32_t T; int needEq;
    radix_select(keys, deadb, false, hist, 96, &T, &needEq, lane);
    if (tid == 0) ctr[0] = 0;
    __syncthreads();
    for (int j = tid; j < D_HID; j += 256) {
        z_out[base + j] = 0.f;
        if (keys[j] >= T) {
            int p = atomicAdd(&ctr[0], 1);
            if (p < NCAND) g_cand[(size_t)r * NCAND + p] = j;
        }
    }
    __syncthreads();
    if (tid == 0) g_cand_n[r] = min(ctr[0], NCAND);
    __syncthreads();

    // ===== aux top-512 among dead features =====
    uint32_t Ta; int needEqA;
    radix_select(keys, deadb, true, hist, KAUX, &Ta, &needEqA, lane);
    if (tid == 0) { ctr[0] = 0; ctr[1] = 0; }
    __syncthreads();
    for (int j = tid; j < D_HID; j += 256) {
        uint32_t k = ((deadb[j >> 5] >> (j & 31)) & 1u) ? keys[j] : 0u;
        if (k != 0u && k == Ta) { int p = atomicAdd(&ctr[1], 1); if (p < 64) eq[p] = j; }
    }
    __syncthreads();
    if (tid == 0) {
        int m = min(ctr[1], 64);
        int take = min(needEqA, m);
        for (int a = 0; a < take; ++a) {
            int best = a;
            for (int b = a + 1; b < m; ++b) if (eq[b] < eq[best]) best = b;
            int t2 = eq[a]; eq[a] = eq[best]; eq[best] = t2;
        }
        ctr[1] = take;
    }
    __syncthreads();
    const int nEqA = ctr[1];
    for (int j = tid; j < D_HID; j += 256) {
        uint32_t k = ((deadb[j >> 5] >> (j & 31)) & 1u) ? keys[j] : 0u;
        bool sel = (k > Ta);
        if (!sel && k != 0u && k == Ta)
            for (int a = 0; a < nEqA; ++a) if (eq[a] == j) { sel = true; break; }
        if (sel) {
            int p = atomicAdd(&ctr[0], 1);
            if (p < KAUX) { g_aux_idx[(size_t)r * KAUX + p] = j; g_aux_val[(size_t)r * KAUX + p] = key2f(keys[j]); }
        }
    }
    __syncthreads();
    if (tid == 0)
        for (int p = min(ctr[0], KAUX); p < KAUX; ++p) {
            g_aux_idx[(size_t)r * KAUX + p] = 0; g_aux_val[(size_t)r * KAUX + p] = -1.f;
        }
}

// ---------------- exact-Eigen refine: recompute candidates, emit bitwise top-64 -----
__global__ __launch_bounds__(128) void refine_kernel(
    const float* __restrict__ X, const float* __restrict__ WE,
    const float* __restrict__ be, const float* __restrict__ bd,
    float* __restrict__ z_out)
{
    __shared__ __align__(16) float xs[D_IN];
    __shared__ float vals[NCAND];
    __shared__ int   idxs[NCAND];
    __shared__ int   l0c;
    const int tid = threadIdx.x, r = blockIdx.x;
    if (tid == 0) l0c = 0;
    for (int k = tid; k < D_IN; k += 128)
        xs[k] = X[(size_t)r * D_IN + k] - bd[k];
    const int n = g_cand_n[r];
    if (tid < n) idxs[tid] = g_cand[(size_t)r * NCAND + tid];
    __syncthreads();

    if (tid < n) {
        const int fi = idxs[tid];
        const float4* w4 = (const float4*)(WE + (size_t)fi * D_IN);
        float acc = 0.f, pan = 0.f;
        int next = 248;
        for (int k = 0; k < D_IN; k += 4) {
            if (k == next) { acc += pan; pan = 0.f; next += 248; }
            float4 w = w4[k >> 2];
            pan = fmaf(xs[k + 0], w.x, pan);
            pan = fmaf(xs[k + 1], w.y, pan);
            pan = fmaf(xs[k + 2], w.z, pan);
            pan = fmaf(xs[k + 3], w.w, pan);
        }
        acc += pan;
        vals[tid] = acc + be[fi];
    }
    __syncthreads();

    if (tid < n) {
        const float v = vals[tid];
        const int myi = idxs[tid];
        int rank = 0;
        for (int j = 0; j < n; ++j) {
            const float u = vals[j];
            if (u > v || (u == v && idxs[j] < myi)) ++rank;
        }
        if (rank < KSEL) {
            g_sel_idx[r * KSEL + rank] = myi;
            g_sel_val[r * KSEL + rank] = v;
            z_out[(size_t)r * D_HID + myi] = fmaxf(v, 0.f);
            if (v > 0.f) atomicAdd(&l0c, 1);
        }
    }
    __syncthreads();
    if (tid == 0) g_l0_p[r] = (float)l0c;
}

// ---------------- sparse decode: x_hat = z @ W_dec^T + b_dec, recon partials --------
__global__ __launch_bounds__(256) void decode_main(const float* __restrict__ X,
                                                   float* __restrict__ xhat,
                                                   const float* __restrict__ bd)
{
    __shared__ int s_idx[KSEL];
    __shared__ float s_val[KSEL];
    __shared__ float red[8];
    const int tid = threadIdx.x, r = blockIdx.x;
    if (tid < KSEL) {
        s_idx[tid] = g_sel_idx[r * KSEL + tid];
        s_val[tid] = fmaxf(g_sel_val[r * KSEL + tid], 0.f);
    }
    __syncthreads();
    const float4* bd4 = (const float4*)bd;
    float4 acc0 = bd4[tid], acc1 = bd4[tid + 256];
    #pragma unroll 4
    for (int s = 0; s < KSEL; ++s) {
        float v = s_val[s];
        const float4* w = (const float4*)(g_WT + (size_t)s_idx[s] * D_IN);
        float4 w0 = w[tid], w1 = w[tid + 256];
        acc0.x += v * w0.x; acc0.y += v * w0.y; acc0.z += v * w0.z; acc0.w += v * w0.w;
        acc1.x += v * w1.x; acc1.y += v * w1.y; acc1.z += v * w1.z; acc1.w += v * w1.w;
    }
    const size_t b4 = (size_t)r * (D_IN / 4);
    ((float4*)xhat)[b4 + tid] = acc0;
    ((float4*)xhat)[b4 + tid + 256] = acc1;
    const float4* X4 = (const float4*)X;
    float4 x0 = X4[b4 + tid], x1 = X4[b4 + tid + 256];
    float d, loc = 0.f;
    d = acc0.x - x0.x; loc += d * d;  d = acc0.y - x0.y; loc += d * d;
    d = acc0.z - x0.z; loc += d * d;  d = acc0.w - x0.w; loc += d * d;
    d = acc1.x - x1.x; loc += d * d;  d = acc1.y - x1.y; loc += d * d;
    d = acc1.z - x1.z; loc += d * d;  d = acc1.w - x1.w; loc += d * d;
    #pragma unroll
    for (int o = 16; o; o >>= 1) loc += __shfl_down_sync(0xFFFFFFFFu, loc, o);
    if ((tid & 31) == 0) red[tid >> 5] = loc;
    __syncthreads();
    if (tid == 0) {
        float s = 0.f;
        for (int w2 = 0; w2 < 8; ++w2) s += red[w2];
        g_recon_p[r] = s;
    }
}

// ---------------- aux decode: e_hat row + aux partials ----------------
__global__ __launch_bounds__(256) void decode_aux(const float* __restrict__ X,
                                                  const float* __restrict__ xhat)
{
    __shared__ int s_idx[KAUX];
    __shared__ float s_val[KAUX];
    __shared__ float red[8];
    const int tid = threadIdx.x, r = blockIdx.x;
    for (int s = tid; s < KAUX; s += 256) {
        s_idx[s] = g_aux_idx[(size_t)r * KAUX + s];
        s_val[s] = fmaxf(g_aux_val[(size_t)r * KAUX + s], 0.f);
    }
    __syncthreads();
    float4 acc0 = make_float4(0.f, 0.f, 0.f, 0.f);
    float4 acc1 = make_float4(0.f, 0.f, 0.f, 0.f);
    #pragma unroll 4
    for (int s = 0; s < KAUX; ++s) {
        float v = s_val[s];
        const float4* w = (const float4*)(g_WT + (size_t)s_idx[s] * D_IN);
        float4 w0 = w[tid], w1 = w[tid + 256];
        acc0.x += v * w0.x; acc0.y += v * w0.y; acc0.z += v * w0.z; acc0.w += v * w0.w;
        acc1.x += v * w1.x; acc1.y += v * w1.y; acc1.z += v * w1.z; acc1.w += v * w1.w;
    }
    const size_t b4 = (size_t)r * (D_IN / 4);
    const float4* X4 = (const float4*)X;
    const float4* H4 = (const float4*)xhat;
    float4 x0 = X4[b4 + tid], x1 = X4[b4 + tid + 256];
    float4 h0 = H4[b4 + tid], h1 = H4[b4 + tid + 256];
    float d, loc = 0.f;
    d = acc0.x - (x0.x - h0.x); loc += d * d;  d = acc0.y - (x0.y - h0.y); loc += d * d;
    d = acc0.z - (x0.z - h0.z); loc += d * d;  d = acc0.w - (x0.w - h0.w); loc += d * d;
    d = acc1.x - (x1.x - h1.x); loc += d * d;  d = acc1.y - (x1.y - h1.y); loc += d * d;
    d = acc1.z - (x1.z - h1.z); loc += d * d;  d = acc1.w - (x1.w - h1.w); loc += d * d;
    #pragma unroll
    for (int o = 16; o; o >>= 1) loc += __shfl_down_sync(0xFFFFFFFFu, loc, o);
    if ((tid & 31) == 0) red[tid >> 5] = loc;
    __syncthreads();
    if (tid == 0) {
        float s = 0.f;
        for (int w2 = 0; w2 < 8; ++w2) s += red[w2];
        g_aux_p[r] = s;
    }
}

// ---------------- final scalar reduction ----------------
__global__ void finalize_kernel(float* __restrict__ outs)
{
    __shared__ double sd[256];
    const int tid = threadIdx.x;
    double s = 0.0;
    for (int i = tid; i < BATCH; i += 256) s += (double)g_recon_p[i];
    sd[tid] = s; __syncthreads();
    for (int o = 128; o > 0; o >>= 1) { if (tid < o) sd[tid] += sd[tid + o]; __syncthreads(); }
    double recon = sd[0] / ((double)BATCH * (double)D_IN);
    __syncthreads();

    s = 0.0;
    for (int i = tid; i < BATCH; i += 256) s += (double)g_aux_p[i];
    sd[tid] = s; __syncthreads();
    for (int o = 128; o > 0; o >>= 1) { if (tid < o) sd[tid] += sd[tid + o]; __syncthreads(); }
    double aux = sd[0] / ((double)BATCH * (double)D_IN);
    __syncthreads();

    s = 0.0;
    for (int i = tid; i < BATCH; i += 256) s += (double)g_l0_p[i];
    sd[tid] = s; __syncthreads();
    for (int o = 128; o > 0; o >>= 1) { if (tid < o) sd[tid] += sd[tid + o]; __syncthreads(); }
    double l0 = sd[0] / (double)BATCH;

    if (tid == 0) {
        outs[0] = (float)(recon + aux * (1.0 / 32.0));
        outs[1] = (float)recon;
        outs[2] = (float)aux;
        outs[3] = (float)l0;
    }
}

// ---------------- launch ----------------
extern "C" void kernel_launch(void* const* d_in, const int* in_sizes, int n_in,
                              void* d_out, int out_size) {
    (void)in_sizes; (void)n_in; (void)out_size;
    const float* X  = (const float*)d_in[0];
    const float* WE = (const float*)d_in[1];
    const float* be = (const float*)d_in[2];
    const float* WD = (const float*)d_in[3];
    const float* bd = (const float*)d_in[4];
    const uint8_t* dm = (const uint8_t*)d_in[5];

    float* out = (float*)d_out;
    float* xhat = out;                                    // [8192, 2048]
    float* z = out + (size_t)BATCH * D_IN;                // [8192, 16384]
    float* scalars = z + (size_t)BATCH * D_HID;           // loss, recon, aux, l0

    cudaFuncSetAttribute(topk_kernel, cudaFuncAttributeMaxDynamicSharedMemorySize, 70 * 1024);

    prep_mask<<<1, 512>>>(dm);
    transpose_wdec<<<dim3(D_HID / 32, D_IN / 32), dim3(32, 8)>>>(WD);
    encoder_mma<<<dim3(D_HID / ENC_BN, BATCH / ENC_BM), 256>>>(X, WE, be, bd);
    topk_kernel<<<BATCH, 256, 70 * 1024>>>(z);
    refine_kernel<<<BATCH, 128>>>(X, WE, be, bd, z);
    decode_main<<<BATCH, 256>>>(X, xhat, bd);
    decode_aux<<<BATCH, 256>>>(X, xhat);
    finalize_kernel<<<1, 256>>>(scalars);
}

// round 9
// speedup vs baseline: 1.3965x; 1.0589x over previous
#include <cuda_runtime.h>
#include <cuda_bf16.h>
#include <cstdint>
#include <math.h>

#define BATCH   8192
#define D_IN    2048
#define D_HID   16384
#define KSEL    64
#define KAUX    512
#define NCAND   128

// ---------------- scratch ----------------
__device__ float    g_pre[(size_t)BATCH * D_HID];
__device__ float    g_WT[(size_t)D_HID * D_IN];            // fp32 W_dec^T (decode_main)
__device__ uint32_t g_WTh[(size_t)D_HID * D_IN / 2];       // bf16x2 W_dec^T (decode_aux)
__device__ int      g_cand[(size_t)BATCH * NCAND];
__device__ int      g_cand_n[BATCH];
__device__ int      g_sel_idx[BATCH * KSEL];
__device__ float    g_sel_val[BATCH * KSEL];
__device__ int      g_aux_idx[(size_t)BATCH * KAUX];
__device__ float    g_aux_val[(size_t)BATCH * KAUX];
__device__ float    g_recon_p[BATCH];
__device__ float    g_aux_p[BATCH];
__device__ float    g_l0_p[BATCH];
__device__ unsigned g_deadbits[D_HID / 32];

// ---------------- helpers ----------------
__device__ __forceinline__ uint32_t f2key(float f) {
    uint32_t u = __float_as_uint(f);
    return (u & 0x80000000u) ? ~u : (u | 0x80000000u);
}
__device__ __forceinline__ float key2f(uint32_t k) {
    uint32_t u = (k & 0x80000000u) ? (k ^ 0x80000000u) : ~k;
    return __uint_as_float(u);
}
__device__ __forceinline__ void split_pair(float x, float y, uint32_t& hp, uint32_t& lp) {
    __nv_bfloat16 hx = __float2bfloat16_rn(x), hy = __float2bfloat16_rn(y);
    float rx = x - __bfloat162float(hx), ry = y - __bfloat162float(hy);
    __nv_bfloat162 h2 = __halves2bfloat162(hx, hy);
    __nv_bfloat162 l2 = __floats2bfloat162_rn(rx, ry);
    hp = *reinterpret_cast<uint32_t*>(&h2);
    lp = *reinterpret_cast<uint32_t*>(&l2);
}
__device__ __forceinline__ void mma_bf16(float c[4], uint32_t a0, uint32_t a1,
                                         uint32_t a2, uint32_t a3,
                                         uint32_t b0, uint32_t b1) {
    asm volatile(
        "mma.sync.aligned.m16n8k16.row.col.f32.bf16.bf16.f32 "
        "{%0,%1,%2,%3}, {%4,%5,%6,%7}, {%8,%9}, {%0,%1,%2,%3};\n"
        : "+f"(c[0]), "+f"(c[1]), "+f"(c[2]), "+f"(c[3])
        : "r"(a0), "r"(a1), "r"(a2), "r"(a3), "r"(b0), "r"(b1));
}
__device__ __forceinline__ void ldsm_x4(uint32_t r[4], uint32_t saddr) {
    asm volatile("ldmatrix.sync.aligned.m8n8.x4.shared.b16 {%0,%1,%2,%3}, [%4];"
        : "=r"(r[0]), "=r"(r[1]), "=r"(r[2]), "=r"(r[3]) : "r"(saddr));
}

// ---------------- dead_mask prep ----------------
__global__ void prep_mask(const uint8_t* __restrict__ m) {
    __shared__ int viol;
    if (threadIdx.x == 0) viol = 0;
    __syncthreads();
    for (int i = threadIdx.x; i < D_HID; i += blockDim.x)
        if ((i & 3) && m[i]) viol = 1;
    __syncthreads();
    const bool is_i32 = (viol == 0);
    const int* mi = (const int*)m;
    for (int w = threadIdx.x; w < D_HID / 32; w += blockDim.x) {
        uint32_t bits = 0;
        #pragma unroll 4
        for (int b = 0; b < 32; ++b) {
            int j = w * 32 + b;
            bool d = is_i32 ? (mi[j] != 0) : (m[j] != 0);
            bits |= ((uint32_t)d) << b;
        }
        g_deadbits[w] = bits;
    }
}

// ---------------- W_dec transpose (fp32) ----------------
__global__ void transpose_wdec(const float* __restrict__ W) {
    __shared__ float t[32][33];
    int x = blockIdx.x * 32 + threadIdx.x;
    int y0 = blockIdx.y * 32;
    #pragma unroll
    for (int i = threadIdx.y; i < 32; i += 8)
        t[i][threadIdx.x] = W[(size_t)(y0 + i) * D_HID + x];
    __syncthreads();
    int xo = y0 + threadIdx.x;
    int yo0 = blockIdx.x * 32;
    #pragma unroll
    for (int i = threadIdx.y; i < 32; i += 8)
        g_WT[(size_t)(yo0 + i) * D_IN + xo] = t[threadIdx.x][i];
}

// ---------------- bf16 conversion of W_dec^T (for aux decode) ----------------
__global__ void convert_wdec_bf16() {
    size_t i = (size_t)blockIdx.x * blockDim.x + threadIdx.x;   // over 16.7M u32
    if (i < (size_t)D_HID * D_IN / 2) {
        float2 f = *(const float2*)(g_WT + 2 * i);
        __nv_bfloat162 b = __floats2bfloat162_rn(f.x, f.y);
        g_WTh[i] = *reinterpret_cast<uint32_t*>(&b);
    }
}

// ---------------- approx encoder: bf16x2 split m16n8k16, ldmatrix fragments ---------
// Same math as R8 (3 products). Smem rows m-major: 16 bf16 data + 8 pad = 48B
// stride (12 u32) -> ldmatrix phases partition all 32 banks (conflict-free).
#define ENC_BM 128
#define ENC_BN 128
#define ROWU   12          // u32 per smem row
#define ARR    (128 * ROWU)  // u32 per array per buffer

__global__ __launch_bounds__(256, 1) void encoder_mma(
    const float* __restrict__ X, const float* __restrict__ WE,
    const float* __restrict__ be, const float* __restrict__ bd)
{
    extern __shared__ uint32_t smem[];
    uint32_t* A1 = smem;               // [2][ARR]
    uint32_t* A2 = smem + 2 * ARR;
    uint32_t* B1 = smem + 4 * ARR;
    uint32_t* B2 = smem + 6 * ARR;

    const int tid = threadIdx.x;
    const int warp = tid >> 5, lane = tid & 31;
    const int wm = warp & 1, wn = warp >> 1;
    const int g = lane >> 2, tg = lane & 3;
    const int i4 = lane >> 3, r8 = lane & 7;
    const int m0 = blockIdx.y * ENC_BM, n0 = blockIdx.x * ENC_BN;

    float c[4][4][4];
    #pragma unroll
    for (int mi = 0; mi < 4; ++mi)
        #pragma unroll
        for (int nj = 0; nj < 4; ++nj)
            #pragma unroll
            for (int q = 0; q < 4; ++q) c[mi][nj][q] = 0.f;

    // per-thread staging slots
    const int srow = tid >> 2;             // handled row for i=0 is srow? (s=tid)
    float4 a_st[2], b_st[2];

    // prologue: load tile 0
    #pragma unroll
    for (int i = 0; i < 2; ++i) {
        int s = tid + i * 256;
        int row = s >> 2, kq = (s & 3) << 2;
        float4 xv = *(const float4*)(X + (size_t)(m0 + row) * D_IN + kq);
        float4 dv = *(const float4*)(bd + kq);
        a_st[i] = make_float4(xv.x - dv.x, xv.y - dv.y, xv.z - dv.z, xv.w - dv.w);
        b_st[i] = *(const float4*)(WE + (size_t)(n0 + row) * D_IN + kq);
    }
    // store tile 0 into buffer 0
    #pragma unroll
    for (int i = 0; i < 2; ++i) {
        int s = tid + i * 256;
        int row = s >> 2, kc2 = (s & 3) << 1;
        uint32_t h0, l0, h1, l1;
        split_pair(a_st[i].x, a_st[i].y, h0, l0);
        split_pair(a_st[i].z, a_st[i].w, h1, l1);
        *(uint2*)(A1 + row * ROWU + kc2) = make_uint2(h0, h1);
        *(uint2*)(A2 + row * ROWU + kc2) = make_uint2(l0, l1);
        split_pair(b_st[i].x, b_st[i].y, h0, l0);
        split_pair(b_st[i].z, b_st[i].w, h1, l1);
        *(uint2*)(B1 + row * ROWU + kc2) = make_uint2(h0, h1);
        *(uint2*)(B2 + row * ROWU + kc2) = make_uint2(l0, l1);
    }
    __syncthreads();
    (void)srow;

    for (int kt = 0; kt < D_IN / 16; ++kt) {
        const int buf = kt & 1;
        const uint32_t bufo = buf * ARR;
        // prefetch next tile from GMEM
        if (kt + 1 < D_IN / 16) {
            int k0 = (kt + 1) * 16;
            #pragma unroll
            for (int i = 0; i < 2; ++i) {
                int s = tid + i * 256;
                int row = s >> 2, kq = ((s & 3) << 2) + k0;
                float4 xv = *(const float4*)(X + (size_t)(m0 + row) * D_IN + kq);
                float4 dv = *(const float4*)(bd + kq);
                a_st[i] = make_float4(xv.x - dv.x, xv.y - dv.y, xv.z - dv.z, xv.w - dv.w);
                b_st[i] = *(const float4*)(WE + (size_t)(n0 + row) * D_IN + kq);
            }
        }
        // ---- compute on buffer buf via ldmatrix ----
        {
            uint32_t a1f[4][4], a2f[4][4], b1f[4][2], b2f[4][2];
            uint32_t a1b = (uint32_t)__cvta_generic_to_shared(A1 + bufo);
            uint32_t a2b = (uint32_t)__cvta_generic_to_shared(A2 + bufo);
            uint32_t b1b = (uint32_t)__cvta_generic_to_shared(B1 + bufo);
            uint32_t b2b = (uint32_t)__cvta_generic_to_shared(B2 + bufo);
            #pragma unroll
            for (int mi = 0; mi < 4; ++mi) {
                int am = wm * 64 + mi * 16 + (i4 & 1) * 8 + r8;
                uint32_t off = (uint32_t)(am * ROWU + (i4 >> 1) * 4) * 4u;
                ldsm_x4(a1f[mi], a1b + off);
                ldsm_x4(a2f[mi], a2b + off);
            }
            #pragma unroll
            for (int nj2 = 0; nj2 < 2; ++nj2) {
                int bn = wn * 32 + (nj2 * 2 + (i4 >> 1)) * 8 + r8;
                uint32_t off = (uint32_t)(bn * ROWU + (i4 & 1) * 4) * 4u;
                uint32_t t1[4], t2[4];
                ldsm_x4(t1, b1b + off);
                ldsm_x4(t2, b2b + off);
                b1f[nj2 * 2][0] = t1[0]; b1f[nj2 * 2][1] = t1[1];
                b1f[nj2 * 2 + 1][0] = t1[2]; b1f[nj2 * 2 + 1][1] = t1[3];
                b2f[nj2 * 2][0] = t2[0]; b2f[nj2 * 2][1] = t2[1];
                b2f[nj2 * 2 + 1][0] = t2[2]; b2f[nj2 * 2 + 1][1] = t2[3];
            }
            #pragma unroll
            for (int nj = 0; nj < 4; ++nj)
                #pragma unroll
                for (int mi = 0; mi < 4; ++mi) {
                    mma_bf16(c[mi][nj], a1f[mi][0], a1f[mi][1], a1f[mi][2], a1f[mi][3],
                             b1f[nj][0], b1f[nj][1]);
                    mma_bf16(c[mi][nj], a1f[mi][0], a1f[mi][1], a1f[mi][2], a1f[mi][3],
                             b2f[nj][0], b2f[nj][1]);
                    mma_bf16(c[mi][nj], a2f[mi][0], a2f[mi][1], a2f[mi][2], a2f[mi][3],
                             b1f[nj][0], b1f[nj][1]);
                }
        }
        // ---- store next tile into the other buffer ----
        if (kt + 1 < D_IN / 16) {
            const uint32_t nbufo = ((kt + 1) & 1) * ARR;
            #pragma unroll
            for (int i = 0; i < 2; ++i) {
                int s = tid + i * 256;
                int row = s >> 2, kc2 = (s & 3) << 1;
                uint32_t h0, l0, h1, l1;
                split_pair(a_st[i].x, a_st[i].y, h0, l0);
                split_pair(a_st[i].z, a_st[i].w, h1, l1);
                *(uint2*)(A1 + nbufo + row * ROWU + kc2) = make_uint2(h0, h1);
                *(uint2*)(A2 + nbufo + row * ROWU + kc2) = make_uint2(l0, l1);
                split_pair(b_st[i].x, b_st[i].y, h0, l0);
                split_pair(b_st[i].z, b_st[i].w, h1, l1);
                *(uint2*)(B1 + nbufo + row * ROWU + kc2) = make_uint2(h0, h1);
                *(uint2*)(B2 + nbufo + row * ROWU + kc2) = make_uint2(l0, l1);
            }
        }
        __syncthreads();
    }

    // epilogue
    #pragma unroll
    for (int mi = 0; mi < 4; ++mi) {
        #pragma unroll
        for (int nj = 0; nj < 4; ++nj) {
            int row0 = m0 + wm * 64 + mi * 16 + g;
            int col = n0 + wn * 32 + nj * 8 + 2 * tg;
            float2 be2 = *(const float2*)(be + col);
            float2 o0 = make_float2(c[mi][nj][0] + be2.x, c[mi][nj][1] + be2.y);
            float2 o1 = make_float2(c[mi][nj][2] + be2.x, c[mi][nj][3] + be2.y);
            *(float2*)&g_pre[(size_t)row0 * D_HID + col] = o0;
            *(float2*)&g_pre[(size_t)(row0 + 8) * D_HID + col] = o1;
        }
    }
}

// ---------------- exact radix-select ----------------
__device__ void radix_select(const uint32_t* keys, const uint32_t* deadb, bool useMask,
                             uint32_t* hist, int K, uint32_t* outT, int* outNeed, int lane)
{
    uint32_t prefix = 0;
    int kk = K;
    #pragma unroll 1
    for (int level = 0; level < 4; ++level) {
        const int shift = 24 - 8 * level;
        for (int b = threadIdx.x; b < 256; b += blockDim.x) hist[b] = 0;
        __syncthreads();
        const uint32_t hmask = (level == 0) ? 0u : (0xFFFFFFFFu << (shift + 8));
        for (int j = threadIdx.x; j < D_HID; j += blockDim.x) {
            uint32_t k = keys[j];
            if (useMask && !((deadb[j >> 5] >> (j & 31)) & 1u)) k = 0u;
            const bool valid = ((k & hmask) == prefix);
            const int bin = (int)((k >> shift) & 255u);
            const int tag = valid ? bin : (256 + lane);
            const unsigned grp = __match_any_sync(0xFFFFFFFFu, tag);
            if (valid && lane == (__ffs(grp) - 1))
                atomicAdd(&hist[bin], (uint32_t)__popc(grp));
        }
        __syncthreads();
        if (threadIdx.x == 0) {
            int acc = 0, b = 255;
            for (; b > 0; --b) {
                int c = (int)hist[b];
                if (acc + c >= kk) break;
                acc += c;
            }
            hist[256] = (uint32_t)b;
            hist[257] = (uint32_t)(kk - acc);
        }
        __syncthreads();
        prefix |= (hist[256] << shift);
        kk = (int)hist[257];
        __syncthreads();
    }
    *outT = prefix;
    *outNeed = kk;
}

// ---------------- per-row: main shortlist (top-96 approx) + aux top-512 -------------
__global__ __launch_bounds__(256) void topk_kernel(float* __restrict__ z_out)
{
    extern __shared__ uint32_t sm[];
    uint32_t* keys  = sm;
    uint32_t* deadb = sm + 16384;
    uint32_t* hist  = sm + 16896;
    int*      eq    = (int*)(sm + 17160);
    int*      ctr   = (int*)(sm + 17224);

    const int tid = threadIdx.x;
    const int lane = tid & 31;
    const int r = blockIdx.x;
    const size_t base = (size_t)r * D_HID;

    for (int j = tid; j < D_HID; j += 256) keys[j] = f2key(g_pre[base + j]);
    for (int w = tid; w < D_HID / 32; w += 256) deadb[w] = g_deadbits[w];
    __syncthreads();

    uint32_t T; int needEq;
    radix_select(keys, deadb, false, hist, 96, &T, &needEq, lane);
    if (tid == 0) ctr[0] = 0;
    __syncthreads();
    for (int j = tid; j < D_HID; j += 256) {
        z_out[base + j] = 0.f;
        if (keys[j] >= T) {
            int p = atomicAdd(&ctr[0], 1);
            if (p < NCAND) g_cand[(size_t)r * NCAND + p] = j;
        }
    }
    __syncthreads();
    if (tid == 0) g_cand_n[r] = min(ctr[0], NCAND);
    __syncthreads();

    uint32_t Ta; int needEqA;
    radix_select(keys, deadb, true, hist, KAUX, &Ta, &needEqA, lane);
    if (tid == 0) { ctr[0] = 0; ctr[1] = 0; }
    __syncthreads();
    for (int j = tid; j < D_HID; j += 256) {
        uint32_t k = ((deadb[j >> 5] >> (j & 31)) & 1u) ? keys[j] : 0u;
        if (k != 0u && k == Ta) { int p = atomicAdd(&ctr[1], 1); if (p < 64) eq[p] = j; }
    }
    __syncthreads();
    if (tid == 0) {
        int m = min(ctr[1], 64);
        int take = min(needEqA, m);
        for (int a = 0; a < take; ++a) {
            int best = a;
            for (int b = a + 1; b < m; ++b) if (eq[b] < eq[best]) best = b;
            int t2 = eq[a]; eq[a] = eq[best]; eq[best] = t2;
        }
        ctr[1] = take;
    }
    __syncthreads();
    const int nEqA = ctr[1];
    for (int j = tid; j < D_HID; j += 256) {
        uint32_t k = ((deadb[j >> 5] >> (j & 31)) & 1u) ? keys[j] : 0u;
        bool sel = (k > Ta);
        if (!sel && k != 0u && k == Ta)
            for (int a = 0; a < nEqA; ++a) if (eq[a] == j) { sel = true; break; }
        if (sel) {
            int p = atomicAdd(&ctr[0], 1);
            if (p < KAUX) { g_aux_idx[(size_t)r * KAUX + p] = j; g_aux_val[(size_t)r * KAUX + p] = key2f(keys[j]); }
        }
    }
    __syncthreads();
    if (tid == 0)
        for (int p = min(ctr[0], KAUX); p < KAUX; ++p) {
            g_aux_idx[(size_t)r * KAUX + p] = 0; g_aux_val[(size_t)r * KAUX + p] = -1.f;
        }
}

// ---------------- exact-Eigen refine (kc=248 panel folds, bitwise-ref values) -------
__global__ __launch_bounds__(128) void refine_kernel(
    const float* __restrict__ X, const float* __restrict__ WE,
    const float* __restrict__ be, const float* __restrict__ bd,
    float* __restrict__ z_out)
{
    __shared__ __align__(16) float xs[D_IN];
    __shared__ float vals[NCAND];
    __shared__ int   idxs[NCAND];
    __shared__ int   l0c;
    const int tid = threadIdx.x, r = blockIdx.x;
    if (tid == 0) l0c = 0;
    for (int k = tid; k < D_IN; k += 128)
        xs[k] = X[(size_t)r * D_IN + k] - bd[k];
    const int n = g_cand_n[r];
    if (tid < n) idxs[tid] = g_cand[(size_t)r * NCAND + tid];
    __syncthreads();

    if (tid < n) {
        const int fi = idxs[tid];
        const float4* w4 = (const float4*)(WE + (size_t)fi * D_IN);
        float acc = 0.f, pan = 0.f;
        int next = 248;
        for (int k = 0; k < D_IN; k += 4) {
            if (k == next) { acc += pan; pan = 0.f; next += 248; }
            float4 w = w4[k >> 2];
            pan = fmaf(xs[k + 0], w.x, pan);
            pan = fmaf(xs[k + 1], w.y, pan);
            pan = fmaf(xs[k + 2], w.z, pan);
            pan = fmaf(xs[k + 3], w.w, pan);
        }
        acc += pan;
        vals[tid] = acc + be[fi];
    }
    __syncthreads();

    if (tid < n) {
        const float v = vals[tid];
        const int myi = idxs[tid];
        int rank = 0;
        for (int j = 0; j < n; ++j) {
            const float u = vals[j];
            if (u > v || (u == v && idxs[j] < myi)) ++rank;
        }
        if (rank < KSEL) {
            g_sel_idx[r * KSEL + rank] = myi;
            g_sel_val[r * KSEL + rank] = v;
            z_out[(size_t)r * D_HID + myi] = fmaxf(v, 0.f);
            if (v > 0.f) atomicAdd(&l0c, 1);
        }
    }
    __syncthreads();
    if (tid == 0) g_l0_p[r] = (float)l0c;
}

// ---------------- sparse decode main (fp32 weights, x_hat exact-class) --------------
__global__ __launch_bounds__(256) void decode_main(const float* __restrict__ X,
                                                   float* __restrict__ xhat,
                                                   const float* __restrict__ bd)
{
    __shared__ int s_idx[KSEL];
    __shared__ float s_val[KSEL];
    __shared__ float red[8];
    const int tid = threadIdx.x, r = blockIdx.x;
    if (tid < KSEL) {
        s_idx[tid] = g_sel_idx[r * KSEL + tid];
        s_val[tid] = fmaxf(g_sel_val[r * KSEL + tid], 0.f);
    }
    __syncthreads();
    const float4* bd4 = (const float4*)bd;
    float4 acc0 = bd4[tid], acc1 = bd4[tid + 256];
    #pragma unroll 4
    for (int s = 0; s < KSEL; ++s) {
        float v = s_val[s];
        const float4* w = (const float4*)(g_WT + (size_t)s_idx[s] * D_IN);
        float4 w0 = w[tid], w1 = w[tid + 256];
        acc0.x += v * w0.x; acc0.y += v * w0.y; acc0.z += v * w0.z; acc0.w += v * w0.w;
        acc1.x += v * w1.x; acc1.y += v * w1.y; acc1.z += v * w1.z; acc1.w += v * w1.w;
    }
    const size_t b4 = (size_t)r * (D_IN / 4);
    ((float4*)xhat)[b4 + tid] = acc0;
    ((float4*)xhat)[b4 + tid + 256] = acc1;
    const float4* X4 = (const float4*)X;
    float4 x0 = X4[b4 + tid], x1 = X4[b4 + tid + 256];
    float d, loc = 0.f;
    d = acc0.x - x0.x; loc += d * d;  d = acc0.y - x0.y; loc += d * d;
    d = acc0.z - x0.z; loc += d * d;  d = acc0.w - x0.w; loc += d * d;
    d = acc1.x - x1.x; loc += d * d;  d = acc1.y - x1.y; loc += d * d;
    d = acc1.z - x1.z; loc += d * d;  d = acc1.w - x1.w; loc += d * d;
    #pragma unroll
    for (int o = 16; o; o >>= 1) loc += __shfl_down_sync(0xFFFFFFFFu, loc, o);
    if ((tid & 31) == 0) red[tid >> 5] = loc;
    __syncthreads();
    if (tid == 0) {
        float s = 0.f;
        for (int w2 = 0; w2 < 8; ++w2) s += red[w2];
        g_recon_p[r] = s;
    }
}

// ---------------- aux decode (bf16 weights): e_hat + aux partials -------------------
__global__ __launch_bounds__(256) void decode_aux(const float* __restrict__ X,
                                                  const float* __restrict__ xhat)
{
    __shared__ int s_idx[KAUX];
    __shared__ float s_val[KAUX];
    __shared__ float red[8];
    const int tid = threadIdx.x, r = blockIdx.x;
    for (int s = tid; s < KAUX; s += 256) {
        s_idx[s] = g_aux_idx[(size_t)r * KAUX + s];
        s_val[s] = fmaxf(g_aux_val[(size_t)r * KAUX + s], 0.f);
    }
    __syncthreads();
    float acc[8];
    #pragma unroll
    for (int e = 0; e < 8; ++e) acc[e] = 0.f;
    #pragma unroll 2
    for (int s = 0; s < KAUX; ++s) {
        float v = s_val[s];
        uint4 w = *((const uint4*)(g_WTh + (size_t)s_idx[s] * (D_IN / 2)) + tid);
        float2 f0 = __bfloat1622float2(*reinterpret_cast<__nv_bfloat162*>(&w.x));
        float2 f1 = __bfloat1622float2(*reinterpret_cast<__nv_bfloat162*>(&w.y));
        float2 f2 = __bfloat1622float2(*reinterpret_cast<__nv_bfloat162*>(&w.z));
        float2 f3 = __bfloat1622float2(*reinterpret_cast<__nv_bfloat162*>(&w.w));
        acc[0] = fmaf(v, f0.x, acc[0]); acc[1] = fmaf(v, f0.y, acc[1]);
        acc[2] = fmaf(v, f1.x, acc[2]); acc[3] = fmaf(v, f1.y, acc[3]);
        acc[4] = fmaf(v, f2.x, acc[4]); acc[5] = fmaf(v, f2.y, acc[5]);
        acc[6] = fmaf(v, f3.x, acc[6]); acc[7] = fmaf(v, f3.y, acc[7]);
    }
    // this thread owns cols tid*8 .. tid*8+7
    const size_t b4 = (size_t)r * (D_IN / 4) + tid * 2;
    const float4* X4 = (const float4*)X;
    const float4* H4 = (const float4*)xhat;
    float4 x0 = X4[b4], x1 = X4[b4 + 1];
    float4 h0 = H4[b4], h1 = H4[b4 + 1];
    float d, loc = 0.f;
    d = acc[0] - (x0.x - h0.x); loc += d * d;  d = acc[1] - (x0.y - h0.y); loc += d * d;
    d = acc[2] - (x0.z - h0.z); loc += d * d;  d = acc[3] - (x0.w - h0.w); loc += d * d;
    d = acc[4] - (x1.x - h1.x); loc += d * d;  d = acc[5] - (x1.y - h1.y); loc += d * d;
    d = acc[6] - (x1.z - h1.z); loc += d * d;  d = acc[7] - (x1.w - h1.w); loc += d * d;
    #pragma unroll
    for (int o = 16; o; o >>= 1) loc += __shfl_down_sync(0xFFFFFFFFu, loc, o);
    if ((tid & 31) == 0) red[tid >> 5] = loc;
    __syncthreads();
    if (tid == 0) {
        float s = 0.f;
        for (int w2 = 0; w2 < 8; ++w2) s += red[w2];
        g_aux_p[r] = s;
    }
}

// ---------------- final scalar reduction ----------------
__global__ void finalize_kernel(float* __restrict__ outs)
{
    __shared__ double sd[256];
    const int tid = threadIdx.x;
    double s = 0.0;
    for (int i = tid; i < BATCH; i += 256) s += (double)g_recon_p[i];
    sd[tid] = s; __syncthreads();
    for (int o = 128; o > 0; o >>= 1) { if (tid < o) sd[tid] += sd[tid + o]; __syncthreads(); }
    double recon = sd[0] / ((double)BATCH * (double)D_IN);
    __syncthreads();

    s = 0.0;
    for (int i = tid; i < BATCH; i += 256) s += (double)g_aux_p[i];
    sd[tid] = s; __syncthreads();
    for (int o = 128; o > 0; o >>= 1) { if (tid < o) sd[tid] += sd[tid + o]; __syncthreads(); }
    double aux = sd[0] / ((double)BATCH * (double)D_IN);
    __syncthreads();

    s = 0.0;
    for (int i = tid; i < BATCH; i += 256) s += (double)g_l0_p[i];
    sd[tid] = s; __syncthreads();
    for (int o = 128; o > 0; o >>= 1) { if (tid < o) sd[tid] += sd[tid + o]; __syncthreads(); }
    double l0 = sd[0] / (double)BATCH;

    if (tid == 0) {
        outs[0] = (float)(recon + aux * (1.0 / 32.0));
        outs[1] = (float)recon;
        outs[2] = (float)aux;
        outs[3] = (float)l0;
    }
}

// ---------------- launch ----------------
extern "C" void kernel_launch(void* const* d_in, const int* in_sizes, int n_in,
                              void* d_out, int out_size) {
    (void)in_sizes; (void)n_in; (void)out_size;
    const float* X  = (const float*)d_in[0];
    const float* WE = (const float*)d_in[1];
    const float* be = (const float*)d_in[2];
    const float* WD = (const float*)d_in[3];
    const float* bd = (const float*)d_in[4];
    const uint8_t* dm = (const uint8_t*)d_in[5];

    float* out = (float*)d_out;
    float* xhat = out;
    float* z = out + (size_t)BATCH * D_IN;
    float* scalars = z + (size_t)BATCH * D_HID;

    cudaFuncSetAttribute(topk_kernel, cudaFuncAttributeMaxDynamicSharedMemorySize, 70 * 1024);
    cudaFuncSetAttribute(encoder_mma, cudaFuncAttributeMaxDynamicSharedMemorySize, 8 * ARR * 4);

    prep_mask<<<1, 512>>>(dm);
    transpose_wdec<<<dim3(D_HID / 32, D_IN / 32), dim3(32, 8)>>>(WD);
    convert_wdec_bf16<<<(unsigned)(((size_t)D_HID * D_IN / 2 + 255) / 256), 256>>>();
    encoder_mma<<<dim3(D_HID / ENC_BN, BATCH / ENC_BM), 256, 8 * ARR * 4>>>(X, WE, be, bd);
    topk_kernel<<<BATCH, 256, 70 * 1024>>>(z);
    refine_kernel<<<BATCH, 128>>>(X, WE, be, bd, z);
    decode_main<<<BATCH, 256>>>(X, xhat, bd);
    decode_aux<<<BATCH, 256>>>(X, xhat);
    finalize_kernel<<<1, 256>>>(scalars);
}

// round 10
// speedup vs baseline: 1.7358x; 1.2430x over previous
#include <cuda_runtime.h>
#include <cuda_bf16.h>
#include <cstdint>
#include <math.h>

#define BATCH   8192
#define D_IN    2048
#define D_HID   16384
#define KSEL    64
#define KAUX    512
#define NCAND   128

// ---------------- scratch ----------------
__device__ float          g_pre[(size_t)BATCH * D_HID];
__device__ float          g_WT[(size_t)D_HID * D_IN];        // fp32 W_dec^T (decode_main)
__device__ uint32_t       g_WTh[(size_t)D_HID * D_IN / 2];   // bf16x2 W_dec^T (decode_aux)
__device__ __nv_bfloat16  g_Xh[(size_t)BATCH * D_IN];        // bf16 split of (x - b_dec)
__device__ __nv_bfloat16  g_Xl[(size_t)BATCH * D_IN];
__device__ __nv_bfloat16  g_Wh[(size_t)D_HID * D_IN];        // bf16 split of W_enc
__device__ __nv_bfloat16  g_Wl[(size_t)D_HID * D_IN];
__device__ int      g_cand[(size_t)BATCH * NCAND];
__device__ int      g_cand_n[BATCH];
__device__ int      g_sel_idx[BATCH * KSEL];
__device__ float    g_sel_val[BATCH * KSEL];
__device__ int      g_aux_idx[(size_t)BATCH * KAUX];
__device__ float    g_aux_val[(size_t)BATCH * KAUX];
__device__ float    g_recon_p[BATCH];
__device__ float    g_aux_p[BATCH];
__device__ float    g_l0_p[BATCH];
__device__ unsigned g_deadbits[D_HID / 32];

// ---------------- helpers ----------------
__device__ __forceinline__ uint32_t f2key(float f) {
    uint32_t u = __float_as_uint(f);
    return (u & 0x80000000u) ? ~u : (u | 0x80000000u);
}
__device__ __forceinline__ float key2f(uint32_t k) {
    uint32_t u = (k & 0x80000000u) ? (k ^ 0x80000000u) : ~k;
    return __uint_as_float(u);
}
__device__ __forceinline__ void mma_bf16(float c[4], uint32_t a0, uint32_t a1,
                                         uint32_t a2, uint32_t a3,
                                         uint32_t b0, uint32_t b1) {
    asm volatile(
        "mma.sync.aligned.m16n8k16.row.col.f32.bf16.bf16.f32 "
        "{%0,%1,%2,%3}, {%4,%5,%6,%7}, {%8,%9}, {%0,%1,%2,%3};\n"
        : "+f"(c[0]), "+f"(c[1]), "+f"(c[2]), "+f"(c[3])
        : "r"(a0), "r"(a1), "r"(a2), "r"(a3), "r"(b0), "r"(b1));
}
__device__ __forceinline__ void ldsm_x4(uint32_t r[4], uint32_t saddr) {
    asm volatile("ldmatrix.sync.aligned.m8n8.x4.shared.b16 {%0,%1,%2,%3}, [%4];"
        : "=r"(r[0]), "=r"(r[1]), "=r"(r[2]), "=r"(r[3]) : "r"(saddr));
}
__device__ __forceinline__ void cp16(uint32_t dst, const void* src) {
    asm volatile("cp.async.cg.shared.global [%0], [%1], 16;" :: "r"(dst), "l"(src));
}

// ---------------- dead_mask prep ----------------
__global__ void prep_mask(const uint8_t* __restrict__ m) {
    __shared__ int viol;
    if (threadIdx.x == 0) viol = 0;
    __syncthreads();
    for (int i = threadIdx.x; i < D_HID; i += blockDim.x)
        if ((i & 3) && m[i]) viol = 1;
    __syncthreads();
    const bool is_i32 = (viol == 0);
    const int* mi = (const int*)m;
    for (int w = threadIdx.x; w < D_HID / 32; w += blockDim.x) {
        uint32_t bits = 0;
        #pragma unroll 4
        for (int b = 0; b < 32; ++b) {
            int j = w * 32 + b;
            bool d = is_i32 ? (mi[j] != 0) : (m[j] != 0);
            bits |= ((uint32_t)d) << b;
        }
        g_deadbits[w] = bits;
    }
}

// ---------------- W_dec transpose (fp32) ----------------
__global__ void transpose_wdec(const float* __restrict__ W) {
    __shared__ float t[32][33];
    int x = blockIdx.x * 32 + threadIdx.x;
    int y0 = blockIdx.y * 32;
    #pragma unroll
    for (int i = threadIdx.y; i < 32; i += 8)
        t[i][threadIdx.x] = W[(size_t)(y0 + i) * D_HID + x];
    __syncthreads();
    int xo = y0 + threadIdx.x;
    int yo0 = blockIdx.x * 32;
    #pragma unroll
    for (int i = threadIdx.y; i < 32; i += 8)
        g_WT[(size_t)(yo0 + i) * D_IN + xo] = t[threadIdx.x][i];
}

// ---------------- bf16 conversion of W_dec^T (aux decode) ----------------
__global__ void convert_wdec_bf16() {
    size_t i = (size_t)blockIdx.x * blockDim.x + threadIdx.x;
    if (i < (size_t)D_HID * D_IN / 2) {
        float2 f = *(const float2*)(g_WT + 2 * i);
        __nv_bfloat162 b = __floats2bfloat162_rn(f.x, f.y);
        g_WTh[i] = *reinterpret_cast<uint32_t*>(&b);
    }
}

// ---------------- precompute bf16 hi/lo splits ----------------
__global__ void split_x(const float* __restrict__ X, const float* __restrict__ bd) {
    size_t i = ((size_t)blockIdx.x * blockDim.x + threadIdx.x) * 4;
    if (i < (size_t)BATCH * D_IN) {
        float4 xv = *(const float4*)(X + i);
        float4 dv = *(const float4*)(bd + (i & (D_IN - 1)));
        float v[4] = {xv.x - dv.x, xv.y - dv.y, xv.z - dv.z, xv.w - dv.w};
        __nv_bfloat16 h[4], l[4];
        #pragma unroll
        for (int e = 0; e < 4; ++e) {
            h[e] = __float2bfloat16_rn(v[e]);
            l[e] = __float2bfloat16_rn(v[e] - __bfloat162float(h[e]));
        }
        *(uint2*)(g_Xh + i) = *(uint2*)h;
        *(uint2*)(g_Xl + i) = *(uint2*)l;
    }
}
__global__ void split_w(const float* __restrict__ WE) {
    size_t i = ((size_t)blockIdx.x * blockDim.x + threadIdx.x) * 4;
    if (i < (size_t)D_HID * D_IN) {
        float4 wv = *(const float4*)(WE + i);
        float v[4] = {wv.x, wv.y, wv.z, wv.w};
        __nv_bfloat16 h[4], l[4];
        #pragma unroll
        for (int e = 0; e < 4; ++e) {
            h[e] = __float2bfloat16_rn(v[e]);
            l[e] = __float2bfloat16_rn(v[e] - __bfloat162float(h[e]));
        }
        *(uint2*)(g_Wh + i) = *(uint2*)h;
        *(uint2*)(g_Wl + i) = *(uint2*)l;
    }
}

// ---------------- approx encoder: bf16x2 split m16n8k16, cp.async + ldmatrix --------
// BK=32, 2-stage cp.async pipeline, 2 CTAs/SM. Row stride 80B -> every ldmatrix
// phase is a perfect 32-bank partition. Math identical to R8/R9 (3 products).
#define ENC_BM 128
#define ENC_BN 128
#define ENC_BK 32
#define ROWU   20                  // u32 per row (64B data + 16B pad)
#define TILEB  (128 * ROWU * 4)    // bytes per array per stage (10240)
#define STAGEB (4 * TILEB)         // bytes per stage (40960)
#define NT     (D_IN / ENC_BK)     // 64 k-tiles

__global__ __launch_bounds__(256, 2) void encoder_mma(const float* __restrict__ be)
{
    extern __shared__ __align__(16) uint32_t smem[];
    const uint32_t sbase = (uint32_t)__cvta_generic_to_shared(smem);

    const int tid = threadIdx.x;
    const int warp = tid >> 5, lane = tid & 31;
    const int wm = warp & 1, wn = warp >> 1;
    const int g = lane >> 2, tg = lane & 3;
    const int i4 = lane >> 3, r8 = lane & 7;
    const int m0 = blockIdx.x * ENC_BM;     // M fast -> A reuse in L2
    const int n0 = blockIdx.y * ENC_BN;

    float c[4][4][4];
    #pragma unroll
    for (int mi = 0; mi < 4; ++mi)
        #pragma unroll
        for (int nj = 0; nj < 4; ++nj)
            #pragma unroll
            for (int q = 0; q < 4; ++q) c[mi][nj][q] = 0.f;

    // per-thread copy slots: idx = tid + j*256 over 512 chunks; row=idx>>2, c16=idx&3
    const int row0 = tid >> 2, c0 = (tid & 3);
    const int row1 = (tid + 256) >> 2, c1 = ((tid + 256) & 3);

    auto issue = [&](int kt) {
        const int k0 = kt * ENC_BK;
        const uint32_t sb = sbase + (kt & 1) * STAGEB;
        {
            uint32_t ro = (uint32_t)(row0 * 80 + c0 * 16);
            const size_t ga = (size_t)(m0 + row0) * D_IN + k0 + c0 * 8;
            const size_t gb = (size_t)(n0 + row0) * D_IN + k0 + c0 * 8;
            cp16(sb + 0 * TILEB + ro, g_Xh + ga);
            cp16(sb + 1 * TILEB + ro, g_Xl + ga);
            cp16(sb + 2 * TILEB + ro, g_Wh + gb);
            cp16(sb + 3 * TILEB + ro, g_Wl + gb);
        }
        {
            uint32_t ro = (uint32_t)(row1 * 80 + c1 * 16);
            const size_t ga = (size_t)(m0 + row1) * D_IN + k0 + c1 * 8;
            const size_t gb = (size_t)(n0 + row1) * D_IN + k0 + c1 * 8;
            cp16(sb + 0 * TILEB + ro, g_Xh + ga);
            cp16(sb + 1 * TILEB + ro, g_Xl + ga);
            cp16(sb + 2 * TILEB + ro, g_Wh + gb);
            cp16(sb + 3 * TILEB + ro, g_Wl + gb);
        }
        asm volatile("cp.async.commit_group;\n" ::: "memory");
    };

    issue(0);
    for (int kt = 0; kt < NT; ++kt) {
        if (kt + 1 < NT) {
            issue(kt + 1);
            asm volatile("cp.async.wait_group 1;\n" ::: "memory");
        } else {
            asm volatile("cp.async.wait_group 0;\n" ::: "memory");
        }
        __syncthreads();

        const uint32_t sb = sbase + (kt & 1) * STAGEB;
        #pragma unroll
        for (int kc = 0; kc < 2; ++kc) {
            uint32_t a1f[4][4], a2f[4][4], b1f[4][2], b2f[4][2];
            #pragma unroll
            for (int mi = 0; mi < 4; ++mi) {
                int am = wm * 64 + mi * 16 + (i4 & 1) * 8 + r8;
                uint32_t off = sb + (uint32_t)(am * 80 + kc * 32 + (i4 >> 1) * 16);
                ldsm_x4(a1f[mi], off);
                ldsm_x4(a2f[mi], off + TILEB);
            }
            #pragma unroll
            for (int nj2 = 0; nj2 < 2; ++nj2) {
                int bn = wn * 32 + (nj2 * 2 + (i4 >> 1)) * 8 + r8;
                uint32_t off = sb + 2 * TILEB +
                               (uint32_t)(bn * 80 + kc * 32 + (i4 & 1) * 16);
                uint32_t t1[4], t2[4];
                ldsm_x4(t1, off);
                ldsm_x4(t2, off + TILEB);
                b1f[nj2 * 2][0] = t1[0]; b1f[nj2 * 2][1] = t1[1];
                b1f[nj2 * 2 + 1][0] = t1[2]; b1f[nj2 * 2 + 1][1] = t1[3];
                b2f[nj2 * 2][0] = t2[0]; b2f[nj2 * 2][1] = t2[1];
                b2f[nj2 * 2 + 1][0] = t2[2]; b2f[nj2 * 2 + 1][1] = t2[3];
            }
            #pragma unroll
            for (int nj = 0; nj < 4; ++nj)
                #pragma unroll
                for (int mi = 0; mi < 4; ++mi) {
                    mma_bf16(c[mi][nj], a1f[mi][0], a1f[mi][1], a1f[mi][2], a1f[mi][3],
                             b1f[nj][0], b1f[nj][1]);
                    mma_bf16(c[mi][nj], a1f[mi][0], a1f[mi][1], a1f[mi][2], a1f[mi][3],
                             b2f[nj][0], b2f[nj][1]);
                    mma_bf16(c[mi][nj], a2f[mi][0], a2f[mi][1], a2f[mi][2], a2f[mi][3],
                             b1f[nj][0], b1f[nj][1]);
                }
        }
        __syncthreads();
    }

    // epilogue
    #pragma unroll
    for (int mi = 0; mi < 4; ++mi) {
        #pragma unroll
        for (int nj = 0; nj < 4; ++nj) {
            int rrow = m0 + wm * 64 + mi * 16 + g;
            int col = n0 + wn * 32 + nj * 8 + 2 * tg;
            float2 be2 = *(const float2*)(be + col);
            float2 o0 = make_float2(c[mi][nj][0] + be2.x, c[mi][nj][1] + be2.y);
            float2 o1 = make_float2(c[mi][nj][2] + be2.x, c[mi][nj][3] + be2.y);
            *(float2*)&g_pre[(size_t)rrow * D_HID + col] = o0;
            *(float2*)&g_pre[(size_t)(rrow + 8) * D_HID + col] = o1;
        }
    }
}

// ---------------- exact radix-select ----------------
__device__ void radix_select(const uint32_t* keys, const uint32_t* deadb, bool useMask,
                             uint32_t* hist, int K, uint32_t* outT, int* outNeed, int lane)
{
    uint32_t prefix = 0;
    int kk = K;
    #pragma unroll 1
    for (int level = 0; level < 4; ++level) {
        const int shift = 24 - 8 * level;
        for (int b = threadIdx.x; b < 256; b += blockDim.x) hist[b] = 0;
        __syncthreads();
        const uint32_t hmask = (level == 0) ? 0u : (0xFFFFFFFFu << (shift + 8));
        for (int j = threadIdx.x; j < D_HID; j += blockDim.x) {
            uint32_t k = keys[j];
            if (useMask && !((deadb[j >> 5] >> (j & 31)) & 1u)) k = 0u;
            const bool valid = ((k & hmask) == prefix);
            const int bin = (int)((k >> shift) & 255u);
            const int tag = valid ? bin : (256 + lane);
            const unsigned grp = __match_any_sync(0xFFFFFFFFu, tag);
            if (valid && lane == (__ffs(grp) - 1))
                atomicAdd(&hist[bin], (uint32_t)__popc(grp));
        }
        __syncthreads();
        if (threadIdx.x == 0) {
            int acc = 0, b = 255;
            for (; b > 0; --b) {
                int c = (int)hist[b];
                if (acc + c >= kk) break;
                acc += c;
            }
            hist[256] = (uint32_t)b;
            hist[257] = (uint32_t)(kk - acc);
        }
        __syncthreads();
        prefix |= (hist[256] << shift);
        kk = (int)hist[257];
        __syncthreads();
    }
    *outT = prefix;
    *outNeed = kk;
}

// ---------------- per-row: main shortlist (top-96 approx) + aux top-512 -------------
__global__ __launch_bounds__(256) void topk_kernel(float* __restrict__ z_out)
{
    extern __shared__ uint32_t sm[];
    uint32_t* keys  = sm;
    uint32_t* deadb = sm + 16384;
    uint32_t* hist  = sm + 16896;
    int*      eq    = (int*)(sm + 17160);
    int*      ctr   = (int*)(sm + 17224);

    const int tid = threadIdx.x;
    const int lane = tid & 31;
    const int r = blockIdx.x;
    const size_t base = (size_t)r * D_HID;

    for (int j = tid; j < D_HID; j += 256) keys[j] = f2key(g_pre[base + j]);
    for (int w = tid; w < D_HID / 32; w += 256) deadb[w] = g_deadbits[w];
    __syncthreads();

    uint32_t T; int needEq;
    radix_select(keys, deadb, false, hist, 96, &T, &needEq, lane);
    if (tid == 0) ctr[0] = 0;
    __syncthreads();
    for (int j = tid; j < D_HID; j += 256) {
        z_out[base + j] = 0.f;
        if (keys[j] >= T) {
            int p = atomicAdd(&ctr[0], 1);
            if (p < NCAND) g_cand[(size_t)r * NCAND + p] = j;
        }
    }
    __syncthreads();
    if (tid == 0) g_cand_n[r] = min(ctr[0], NCAND);
    __syncthreads();

    uint32_t Ta; int needEqA;
    radix_select(keys, deadb, true, hist, KAUX, &Ta, &needEqA, lane);
    if (tid == 0) { ctr[0] = 0; ctr[1] = 0; }
    __syncthreads();
    for (int j = tid; j < D_HID; j += 256) {
        uint32_t k = ((deadb[j >> 5] >> (j & 31)) & 1u) ? keys[j] : 0u;
        if (k != 0u && k == Ta) { int p = atomicAdd(&ctr[1], 1); if (p < 64) eq[p] = j; }
    }
    __syncthreads();
    if (tid == 0) {
        int m = min(ctr[1], 64);
        int take = min(needEqA, m);
        for (int a = 0; a < take; ++a) {
            int best = a;
            for (int b = a + 1; b < m; ++b) if (eq[b] < eq[best]) best = b;
            int t2 = eq[a]; eq[a] = eq[best]; eq[best] = t2;
        }
        ctr[1] = take;
    }
    __syncthreads();
    const int nEqA = ctr[1];
    for (int j = tid; j < D_HID; j += 256) {
        uint32_t k = ((deadb[j >> 5] >> (j & 31)) & 1u) ? keys[j] : 0u;
        bool sel = (k > Ta);
        if (!sel && k != 0u && k == Ta)
            for (int a = 0; a < nEqA; ++a) if (eq[a] == j) { sel = true; break; }
        if (sel) {
            int p = atomicAdd(&ctr[0], 1);
            if (p < KAUX) { g_aux_idx[(size_t)r * KAUX + p] = j; g_aux_val[(size_t)r * KAUX + p] = key2f(keys[j]); }
        }
    }
    __syncthreads();
    if (tid == 0)
        for (int p = min(ctr[0], KAUX); p < KAUX; ++p) {
            g_aux_idx[(size_t)r * KAUX + p] = 0; g_aux_val[(size_t)r * KAUX + p] = -1.f;
        }
}

// ---------------- exact-Eigen refine (kc=248 panel folds, bitwise-ref values) -------
__global__ __launch_bounds__(128) void refine_kernel(
    const float* __restrict__ X, const float* __restrict__ WE,
    const float* __restrict__ be, const float* __restrict__ bd,
    float* __restrict__ z_out)
{
    __shared__ __align__(16) float xs[D_IN];
    __shared__ float vals[NCAND];
    __shared__ int   idxs[NCAND];
    __shared__ int   l0c;
    const int tid = threadIdx.x, r = blockIdx.x;
    if (tid == 0) l0c = 0;
    for (int k = tid; k < D_IN; k += 128)
        xs[k] = X[(size_t)r * D_IN + k] - bd[k];
    const int n = g_cand_n[r];
    if (tid < n) idxs[tid] = g_cand[(size_t)r * NCAND + tid];
    __syncthreads();

    if (tid < n) {
        const int fi = idxs[tid];
        const float4* w4 = (const float4*)(WE + (size_t)fi * D_IN);
        float acc = 0.f, pan = 0.f;
        int next = 248;
        for (int k = 0; k < D_IN; k += 4) {
            if (k == next) { acc += pan; pan = 0.f; next += 248; }
            float4 w = w4[k >> 2];
            pan = fmaf(xs[k + 0], w.x, pan);
            pan = fmaf(xs[k + 1], w.y, pan);
            pan = fmaf(xs[k + 2], w.z, pan);
            pan = fmaf(xs[k + 3], w.w, pan);
        }
        acc += pan;
        vals[tid] = acc + be[fi];
    }
    __syncthreads();

    if (tid < n) {
        const float v = vals[tid];
        const int myi = idxs[tid];
        int rank = 0;
        for (int j = 0; j < n; ++j) {
            const float u = vals[j];
            if (u > v || (u == v && idxs[j] < myi)) ++rank;
        }
        if (rank < KSEL) {
            g_sel_idx[r * KSEL + rank] = myi;
            g_sel_val[r * KSEL + rank] = v;
            z_out[(size_t)r * D_HID + myi] = fmaxf(v, 0.f);
            if (v > 0.f) atomicAdd(&l0c, 1);
        }
    }
    __syncthreads();
    if (tid == 0) g_l0_p[r] = (float)l0c;
}

// ---------------- sparse decode main (fp32 weights) ----------------
__global__ __launch_bounds__(256) void decode_main(const float* __restrict__ X,
                                                   float* __restrict__ xhat,
                                                   const float* __restrict__ bd)
{
    __shared__ int s_idx[KSEL];
    __shared__ float s_val[KSEL];
    __shared__ float red[8];
    const int tid = threadIdx.x, r = blockIdx.x;
    if (tid < KSEL) {
        s_idx[tid] = g_sel_idx[r * KSEL + tid];
        s_val[tid] = fmaxf(g_sel_val[r * KSEL + tid], 0.f);
    }
    __syncthreads();
    const float4* bd4 = (const float4*)bd;
    float4 acc0 = bd4[tid], acc1 = bd4[tid + 256];
    #pragma unroll 4
    for (int s = 0; s < KSEL; ++s) {
        float v = s_val[s];
        const float4* w = (const float4*)(g_WT + (size_t)s_idx[s] * D_IN);
        float4 w0 = w[tid], w1 = w[tid + 256];
        acc0.x += v * w0.x; acc0.y += v * w0.y; acc0.z += v * w0.z; acc0.w += v * w0.w;
        acc1.x += v * w1.x; acc1.y += v * w1.y; acc1.z += v * w1.z; acc1.w += v * w1.w;
    }
    const size_t b4 = (size_t)r * (D_IN / 4);
    ((float4*)xhat)[b4 + tid] = acc0;
    ((float4*)xhat)[b4 + tid + 256] = acc1;
    const float4* X4 = (const float4*)X;
    float4 x0 = X4[b4 + tid], x1 = X4[b4 + tid + 256];
    float d, loc = 0.f;
    d = acc0.x - x0.x; loc += d * d;  d = acc0.y - x0.y; loc += d * d;
    d = acc0.z - x0.z; loc += d * d;  d = acc0.w - x0.w; loc += d * d;
    d = acc1.x - x1.x; loc += d * d;  d = acc1.y - x1.y; loc += d * d;
    d = acc1.z - x1.z; loc += d * d;  d = acc1.w - x1.w; loc += d * d;
    #pragma unroll
    for (int o = 16; o; o >>= 1) loc += __shfl_down_sync(0xFFFFFFFFu, loc, o);
    if ((tid & 31) == 0) red[tid >> 5] = loc;
    __syncthreads();
    if (tid == 0) {
        float s = 0.f;
        for (int w2 = 0; w2 < 8; ++w2) s += red[w2];
        g_recon_p[r] = s;
    }
}

// ---------------- aux decode (bf16 weights) ----------------
__global__ __launch_bounds__(256) void decode_aux(const float* __restrict__ X,
                                                  const float* __restrict__ xhat)
{
    __shared__ int s_idx[KAUX];
    __shared__ float s_val[KAUX];
    __shared__ float red[8];
    const int tid = threadIdx.x, r = blockIdx.x;
    for (int s = tid; s < KAUX; s += 256) {
        s_idx[s] = g_aux_idx[(size_t)r * KAUX + s];
        s_val[s] = fmaxf(g_aux_val[(size_t)r * KAUX + s], 0.f);
    }
    __syncthreads();
    float acc[8];
    #pragma unroll
    for (int e = 0; e < 8; ++e) acc[e] = 0.f;
    #pragma unroll 2
    for (int s = 0; s < KAUX; ++s) {
        float v = s_val[s];
        uint4 w = *((const uint4*)(g_WTh + (size_t)s_idx[s] * (D_IN / 2)) + tid);
        float2 f0 = __bfloat1622float2(*reinterpret_cast<__nv_bfloat162*>(&w.x));
        float2 f1 = __bfloat1622float2(*reinterpret_cast<__nv_bfloat162*>(&w.y));
        float2 f2 = __bfloat1622float2(*reinterpret_cast<__nv_bfloat162*>(&w.z));
        float2 f3 = __bfloat1622float2(*reinterpret_cast<__nv_bfloat162*>(&w.w));
        acc[0] = fmaf(v, f0.x, acc[0]); acc[1] = fmaf(v, f0.y, acc[1]);
        acc[2] = fmaf(v, f1.x, acc[2]); acc[3] = fmaf(v, f1.y, acc[3]);
        acc[4] = fmaf(v, f2.x, acc[4]); acc[5] = fmaf(v, f2.y, acc[5]);
        acc[6] = fmaf(v, f3.x, acc[6]); acc[7] = fmaf(v, f3.y, acc[7]);
    }
    const size_t b4 = (size_t)r * (D_IN / 4) + tid * 2;
    const float4* X4 = (const float4*)X;
    const float4* H4 = (const float4*)xhat;
    float4 x0 = X4[b4], x1 = X4[b4 + 1];
    float4 h0 = H4[b4], h1 = H4[b4 + 1];
    float d, loc = 0.f;
    d = acc[0] - (x0.x - h0.x); loc += d * d;  d = acc[1] - (x0.y - h0.y); loc += d * d;
    d = acc[2] - (x0.z - h0.z); loc += d * d;  d = acc[3] - (x0.w - h0.w); loc += d * d;
    d = acc[4] - (x1.x - h1.x); loc += d * d;  d = acc[5] - (x1.y - h1.y); loc += d * d;
    d = acc[6] - (x1.z - h1.z); loc += d * d;  d = acc[7] - (x1.w - h1.w); loc += d * d;
    #pragma unroll
    for (int o = 16; o; o >>= 1) loc += __shfl_down_sync(0xFFFFFFFFu, loc, o);
    if ((tid & 31) == 0) red[tid >> 5] = loc;
    __syncthreads();
    if (tid == 0) {
        float s = 0.f;
        for (int w2 = 0; w2 < 8; ++w2) s += red[w2];
        g_aux_p[r] = s;
    }
}

// ---------------- final scalar reduction ----------------
__global__ void finalize_kernel(float* __restrict__ outs)
{
    __shared__ double sd[256];
    const int tid = threadIdx.x;
    double s = 0.0;
    for (int i = tid; i < BATCH; i += 256) s += (double)g_recon_p[i];
    sd[tid] = s; __syncthreads();
    for (int o = 128; o > 0; o >>= 1) { if (tid < o) sd[tid] += sd[tid + o]; __syncthreads(); }
    double recon = sd[0] / ((double)BATCH * (double)D_IN);
    __syncthreads();

    s = 0.0;
    for (int i = tid; i < BATCH; i += 256) s += (double)g_aux_p[i];
    sd[tid] = s; __syncthreads();
    for (int o = 128; o > 0; o >>= 1) { if (tid < o) sd[tid] += sd[tid + o]; __syncthreads(); }
    double aux = sd[0] / ((double)BATCH * (double)D_IN);
    __syncthreads();

    s = 0.0;
    for (int i = tid; i < BATCH; i += 256) s += (double)g_l0_p[i];
    sd[tid] = s; __syncthreads();
    for (int o = 128; o > 0; o >>= 1) { if (tid < o) sd[tid] += sd[tid + o]; __syncthreads(); }
    double l0 = sd[0] / (double)BATCH;

    if (tid == 0) {
        outs[0] = (float)(recon + aux * (1.0 / 32.0));
        outs[1] = (float)recon;
        outs[2] = (float)aux;
        outs[3] = (float)l0;
    }
}

// ---------------- launch ----------------
extern "C" void kernel_launch(void* const* d_in, const int* in_sizes, int n_in,
                              void* d_out, int out_size) {
    (void)in_sizes; (void)n_in; (void)out_size;
    const float* X  = (const float*)d_in[0];
    const float* WE = (const float*)d_in[1];
    const float* be = (const float*)d_in[2];
    const float* WD = (const float*)d_in[3];
    const float* bd = (const float*)d_in[4];
    const uint8_t* dm = (const uint8_t*)d_in[5];

    float* out = (float*)d_out;
    float* xhat = out;
    float* z = out + (size_t)BATCH * D_IN;
    float* scalars = z + (size_t)BATCH * D_HID;

    cudaFuncSetAttribute(topk_kernel, cudaFuncAttributeMaxDynamicSharedMemorySize, 70 * 1024);
    cudaFuncSetAttribute(encoder_mma, cudaFuncAttributeMaxDynamicSharedMemorySize, 2 * STAGEB);

    prep_mask<<<1, 512>>>(dm);
    transpose_wdec<<<dim3(D_HID / 32, D_IN / 32), dim3(32, 8)>>>(WD);
    convert_wdec_bf16<<<(unsigned)(((size_t)D_HID * D_IN / 2 + 255) / 256), 256>>>();
    split_x<<<(unsigned)(((size_t)BATCH * D_IN / 4 + 255) / 256), 256>>>(X, bd);
    split_w<<<(unsigned)(((size_t)D_HID * D_IN / 4 + 255) / 256), 256>>>(WE);
    encoder_mma<<<dim3(BATCH / ENC_BM, D_HID / ENC_BN), 256, 2 * STAGEB>>>(be);
    topk_kernel<<<BATCH, 256, 70 * 1024>>>(z);
    refine_kernel<<<BATCH, 128>>>(X, WE, be, bd, z);
    decode_main<<<BATCH, 256>>>(X, xhat, bd);
    decode_aux<<<BATCH, 256>>>(X, xhat);
    finalize_kernel<<<1, 256>>>(scalars);
}